// round 1
// baseline (speedup 1.0000x reference)
#include <cuda_runtime.h>
#include <math.h>
#include <stddef.h>

// Problem dims (fixed by reference)
constexpr int Bn  = 2;
constexpr int Sn  = 2048;
constexpr int Dn  = 512;
constexpr int Hn  = 8;
constexpr int DKn = 64;
constexpr int DFFn= 2048;
constexpr int BSn = Bn * Sn;          // 4096 token rows

// ---------------- scratch (device globals; no allocation allowed) ----------
__device__ float g_q  [BSn * Dn];
__device__ float g_k  [BSn * Dn];
__device__ float g_v  [BSn * Dn];
__device__ float g_ctx[BSn * Dn];
__device__ float g_x1 [BSn * Dn];
__device__ float g_t2 [BSn * Dn];     // attn_out / ff_out staging
__device__ float g_ff [BSn * DFFn];   // gelu hidden

// ---------------------------------------------------------------------------
// SGEMM: C[M,N] = A[M,K] @ B[K,N] (+bias) (+gelu).  128x128x8, 8x8 microtile.
// EPI: 0 = none, 1 = +bias, 2 = +bias then exact gelu
// M%128==0, N%128==0, K%8==0, K%4==0 assumed (true for all calls).
// ---------------------------------------------------------------------------
template<int EPI>
__global__ __launch_bounds__(256)
void sgemm(const float* __restrict__ A, const float* __restrict__ Bm,
           const float* __restrict__ bias, float* __restrict__ C,
           int M, int N, int K)
{
    __shared__ float As[8][128];
    __shared__ float Bs[8][128];

    const int tid = threadIdx.x;
    const int bx = blockIdx.x, by = blockIdx.y;
    const int tx = tid & 15, ty = tid >> 4;
    const int row0 = by * 128 + ty * 8;
    const int col0 = bx * 128 + tx * 8;

    const int a_r = tid >> 1;            // 0..127
    const int a_k = (tid & 1) << 2;      // 0 or 4
    const int b_k = tid >> 5;            // 0..7
    const int b_c = (tid & 31) << 2;     // 0..124

    float acc[8][8];
    #pragma unroll
    for (int i = 0; i < 8; i++)
        #pragma unroll
        for (int j = 0; j < 8; j++) acc[i][j] = 0.f;

    for (int k0 = 0; k0 < K; k0 += 8) {
        float4 av = *(const float4*)&A[(size_t)(by*128 + a_r) * K + k0 + a_k];
        float4 bv = *(const float4*)&Bm[(size_t)(k0 + b_k) * N + bx*128 + b_c];
        __syncthreads();
        As[a_k+0][a_r] = av.x;
        As[a_k+1][a_r] = av.y;
        As[a_k+2][a_r] = av.z;
        As[a_k+3][a_r] = av.w;
        *(float4*)&Bs[b_k][b_c] = bv;
        __syncthreads();
        #pragma unroll
        for (int kk = 0; kk < 8; kk++) {
            float a8[8], b8[8];
            *(float4*)&a8[0] = *(const float4*)&As[kk][ty*8];
            *(float4*)&a8[4] = *(const float4*)&As[kk][ty*8+4];
            *(float4*)&b8[0] = *(const float4*)&Bs[kk][tx*8];
            *(float4*)&b8[4] = *(const float4*)&Bs[kk][tx*8+4];
            #pragma unroll
            for (int i = 0; i < 8; i++)
                #pragma unroll
                for (int j = 0; j < 8; j++)
                    acc[i][j] += a8[i] * b8[j];
        }
    }

    float bb[8];
    if (EPI >= 1) {
        #pragma unroll
        for (int j = 0; j < 8; j++) bb[j] = bias[col0 + j];
    }
    #pragma unroll
    for (int i = 0; i < 8; i++) {
        float out8[8];
        #pragma unroll
        for (int j = 0; j < 8; j++) {
            float v = acc[i][j];
            if (EPI >= 1) v += bb[j];
            if (EPI == 2) v = 0.5f * v * (1.0f + erff(v * 0.70710678118654752f));
            out8[j] = v;
        }
        float* crow = C + (size_t)(row0 + i) * N + col0;
        *(float4*)&crow[0] = *(float4*)&out8[0];
        *(float4*)&crow[4] = *(float4*)&out8[4];
    }
}

// ---------------------------------------------------------------------------
// Fused attention: scores -> (+bias, mask) -> softmax -> write attn -> PV.
// One CTA handles 16 query rows for one (b,h). Scores block stays in SMEM.
// ---------------------------------------------------------------------------
constexpr int QT = 16;                 // query rows per CTA
constexpr int CN = 256;                // k-chunk size
constexpr int VSTRIDE = 68;            // padded V smem row
constexpr int SCORE_F = QT * Sn;       // 32768 floats
constexpr int QS_F    = DKn * QT;      // 1024 floats
constexpr int KV_F    = CN * VSTRIDE;  // 17408 floats (>= 64*256 for K)
constexpr int ATTN_SMEM_BYTES = (SCORE_F + QS_F + KV_F) * (int)sizeof(float); // 204800

__global__ __launch_bounds__(256)
void attn_kernel(const float* __restrict__ q, const float* __restrict__ k,
                 const float* __restrict__ v, const float* __restrict__ sw,
                 const int* __restrict__ mask, const float* __restrict__ sa,
                 const float* __restrict__ tb,
                 float* __restrict__ attn_out, float* __restrict__ ctx)
{
    extern __shared__ float sm[];
    float* s_sc = sm;                  // [QT][Sn]
    float* s_q  = sm + SCORE_F;        // [DKn][QT] transposed Q
    float* s_kv = s_q + QS_F;          // K chunk [DKn][CN] / V chunk [CN][VSTRIDE]
    __shared__ float s_bias[QT];

    const int tid = threadIdx.x;
    const int qt = blockIdx.x, h = blockIdx.y, b = blockIdx.z;
    const int q0 = qt * QT;

    // load Q tile transposed: s_q[d][r]
    for (int i = tid; i < QT * DKn; i += 256) {
        int r = i >> 6, d = i & 63;
        s_q[d * QT + r] = q[((size_t)(b*Sn + q0 + r)) * Dn + h*DKn + d];
    }
    if (tid < QT) {
        const float* swp = sw + ((size_t)(b*Sn) + q0 + tid) * 4;
        const float* sap = sa + h * 4;
        s_bias[tid] = tb[h] + sap[0]*swp[0] + sap[1]*swp[1]
                            + sap[2]*swp[2] + sap[3]*swp[3];
    }

    // ---------------- score phase: S = QK^T/8 + bias, masked ----------------
    const int ty = tid >> 6;           // 0..3   -> rows 4*ty..4*ty+3
    const int tx = tid & 63;           // 0..63  -> cols 4*tx..4*tx+3 in chunk
    for (int c0 = 0; c0 < Sn; c0 += CN) {
        __syncthreads();               // s_kv free / s_q ready
        // load K chunk transposed: s_kv[d][c]
        #pragma unroll
        for (int it = 0; it < 16; it++) {
            int idx = tid + it * 256;
            int c = idx >> 4, d4 = (idx & 15) << 2;
            float4 kv4 = *(const float4*)&k[((size_t)(b*Sn + c0 + c)) * Dn + h*DKn + d4];
            s_kv[(d4+0)*CN + c] = kv4.x;
            s_kv[(d4+1)*CN + c] = kv4.y;
            s_kv[(d4+2)*CN + c] = kv4.z;
            s_kv[(d4+3)*CN + c] = kv4.w;
        }
        __syncthreads();
        float acc[4][4];
        #pragma unroll
        for (int i = 0; i < 4; i++)
            #pragma unroll
            for (int j = 0; j < 4; j++) acc[i][j] = 0.f;
        #pragma unroll
        for (int d = 0; d < DKn; d++) {
            float4 a4 = *(const float4*)&s_q[d*QT + 4*ty];
            float4 b4 = *(const float4*)&s_kv[d*CN + 4*tx];
            acc[0][0] += a4.x*b4.x; acc[0][1] += a4.x*b4.y; acc[0][2] += a4.x*b4.z; acc[0][3] += a4.x*b4.w;
            acc[1][0] += a4.y*b4.x; acc[1][1] += a4.y*b4.y; acc[1][2] += a4.y*b4.z; acc[1][3] += a4.y*b4.w;
            acc[2][0] += a4.z*b4.x; acc[2][1] += a4.z*b4.y; acc[2][2] += a4.z*b4.z; acc[2][3] += a4.z*b4.w;
            acc[3][0] += a4.w*b4.x; acc[3][1] += a4.w*b4.y; acc[3][2] += a4.w*b4.z; acc[3][3] += a4.w*b4.w;
        }
        #pragma unroll
        for (int i = 0; i < 4; i++) {
            int rr = 4*ty + i;
            #pragma unroll
            for (int j = 0; j < 4; j++) {
                int cc = c0 + 4*tx + j;
                float val = acc[i][j] * 0.125f + s_bias[rr];
                if (mask[(size_t)(q0 + rr) * Sn + cc] == 0) val = -1e9f;
                s_sc[rr * Sn + cc] = val;
            }
        }
    }
    __syncthreads();

    // ---------------- softmax (warp handles 2 rows) + write attn -----------
    {
        int w = tid >> 5, lane = tid & 31;
        for (int r = 2*w; r < 2*w + 2; r++) {
            float* sp = s_sc + r * Sn;
            float m = -3.4e38f;
            for (int kk = lane; kk < Sn; kk += 32) m = fmaxf(m, sp[kk]);
            #pragma unroll
            for (int o = 16; o > 0; o >>= 1) m = fmaxf(m, __shfl_xor_sync(0xffffffffu, m, o));
            float s = 0.f;
            for (int kk = lane; kk < Sn; kk += 32) {
                float p = expf(sp[kk] - m);
                sp[kk] = p;
                s += p;
            }
            #pragma unroll
            for (int o = 16; o > 0; o >>= 1) s += __shfl_xor_sync(0xffffffffu, s, o);
            float inv = 1.f / s;
            float* ap = attn_out + ((size_t)((b*Hn + h)*Sn + q0 + r)) * Sn;
            for (int kk = lane; kk < Sn; kk += 32) {
                float p = sp[kk] * inv;
                sp[kk] = p;
                ap[kk] = p;
            }
        }
    }
    __syncthreads();

    // ---------------- PV phase: ctx = attn @ V ------------------------------
    const int ry = tid >> 4;           // 0..15 row
    const int cx = (tid & 15) << 2;    // col base 0..60
    float o0 = 0.f, o1 = 0.f, o2 = 0.f, o3 = 0.f;
    for (int c0 = 0; c0 < Sn; c0 += CN) {
        // load V chunk: s_kv[c][d] (padded stride)
        #pragma unroll
        for (int it = 0; it < 16; it++) {
            int idx = tid + it * 256;
            int c = idx >> 4, d4 = (idx & 15) << 2;
            float4 vv = *(const float4*)&v[((size_t)(b*Sn + c0 + c)) * Dn + h*DKn + d4];
            *(float4*)&s_kv[c * VSTRIDE + d4] = vv;
        }
        __syncthreads();
        #pragma unroll 8
        for (int kk = 0; kk < CN; kk++) {
            float a = s_sc[ry * Sn + c0 + kk];
            float4 b4 = *(const float4*)&s_kv[kk * VSTRIDE + cx];
            o0 += a * b4.x; o1 += a * b4.y; o2 += a * b4.z; o3 += a * b4.w;
        }
        __syncthreads();
    }
    float* cp = ctx + ((size_t)(b*Sn + q0 + ry)) * Dn + h*DKn + cx;
    cp[0] = o0; cp[1] = o1; cp[2] = o2; cp[3] = o3;
}

// ---------------------------------------------------------------------------
// out = LayerNorm(a + r) * g + b    (one CTA per 512-wide row, 256 threads)
// ---------------------------------------------------------------------------
__global__ __launch_bounds__(256)
void add_ln(const float* __restrict__ a, const float* __restrict__ r,
            const float* __restrict__ g, const float* __restrict__ be,
            float* __restrict__ out)
{
    const int row = blockIdx.x, tid = threadIdx.x;
    const float* ap = a + (size_t)row * Dn;
    const float* rp = r + (size_t)row * Dn;
    float v0 = ap[tid]       + rp[tid];
    float v1 = ap[tid + 256] + rp[tid + 256];

    __shared__ float red[8];
    __shared__ float s_mu, s_inv;
    const int w = tid >> 5, lane = tid & 31;

    float s = v0 + v1;
    #pragma unroll
    for (int o = 16; o > 0; o >>= 1) s += __shfl_xor_sync(0xffffffffu, s, o);
    if (lane == 0) red[w] = s;
    __syncthreads();
    if (tid < 32) {
        float t = (tid < 8) ? red[tid] : 0.f;
        #pragma unroll
        for (int o = 4; o > 0; o >>= 1) t += __shfl_xor_sync(0xffffffffu, t, o);
        if (tid == 0) s_mu = t * (1.f / Dn);
    }
    __syncthreads();
    float mu = s_mu;
    float d0 = v0 - mu, d1 = v1 - mu;

    float q = d0*d0 + d1*d1;
    #pragma unroll
    for (int o = 16; o > 0; o >>= 1) q += __shfl_xor_sync(0xffffffffu, q, o);
    __syncthreads();                 // red[] reuse
    if (lane == 0) red[w] = q;
    __syncthreads();
    if (tid < 32) {
        float t = (tid < 8) ? red[tid] : 0.f;
        #pragma unroll
        for (int o = 4; o > 0; o >>= 1) t += __shfl_xor_sync(0xffffffffu, t, o);
        if (tid == 0) s_inv = rsqrtf(t * (1.f / Dn) + 1e-6f);
    }
    __syncthreads();
    float inv = s_inv;
    float* op = out + (size_t)row * Dn;
    op[tid]       = d0 * inv * g[tid]       + be[tid];
    op[tid + 256] = d1 * inv * g[tid + 256] + be[tid + 256];
}

// ---------------------------------------------------------------------------
extern "C" void kernel_launch(void* const* d_in, const int* in_sizes, int n_in,
                              void* d_out, int out_size)
{
    const float* x    = (const float*)d_in[0];
    const float* sw   = (const float*)d_in[1];
    const int*   mask = (const int*)  d_in[2];
    const float* Wq   = (const float*)d_in[3];
    const float* Wk   = (const float*)d_in[4];
    const float* Wv   = (const float*)d_in[5];
    const float* Wo   = (const float*)d_in[6];
    const float* bo   = (const float*)d_in[7];
    const float* sa   = (const float*)d_in[8];
    const float* tb   = (const float*)d_in[9];
    const float* ln1g = (const float*)d_in[10];
    const float* ln1b = (const float*)d_in[11];
    const float* ln2g = (const float*)d_in[12];
    const float* ln2b = (const float*)d_in[13];
    const float* W1   = (const float*)d_in[14];
    const float* b1   = (const float*)d_in[15];
    const float* W2   = (const float*)d_in[16];
    const float* b2   = (const float*)d_in[17];

    float* out_x2   = (float*)d_out;
    float* out_attn = (float*)d_out + (size_t)BSn * Dn;

    float *q, *k, *v, *ctx, *x1, *t2, *ff;
    cudaGetSymbolAddress((void**)&q,   g_q);
    cudaGetSymbolAddress((void**)&k,   g_k);
    cudaGetSymbolAddress((void**)&v,   g_v);
    cudaGetSymbolAddress((void**)&ctx, g_ctx);
    cudaGetSymbolAddress((void**)&x1,  g_x1);
    cudaGetSymbolAddress((void**)&t2,  g_t2);
    cudaGetSymbolAddress((void**)&ff,  g_ff);

    cudaFuncSetAttribute(attn_kernel,
                         cudaFuncAttributeMaxDynamicSharedMemorySize,
                         ATTN_SMEM_BYTES);

    dim3 gP(Dn / 128, BSn / 128);      // (4, 32) projections
    dim3 gF1(DFFn / 128, BSn / 128);   // (16, 32) ffn1
    dim3 blk(256);

    // QKV projections
    sgemm<0><<<gP, blk>>>(x, Wq, nullptr, q, BSn, Dn, Dn);
    sgemm<0><<<gP, blk>>>(x, Wk, nullptr, k, BSn, Dn, Dn);
    sgemm<0><<<gP, blk>>>(x, Wv, nullptr, v, BSn, Dn, Dn);

    // fused attention: scores+softmax+attn write+PV
    attn_kernel<<<dim3(Sn / QT, Hn, Bn), blk, ATTN_SMEM_BYTES>>>(
        q, k, v, sw, mask, sa, tb, out_attn, ctx);

    // output projection + bias
    sgemm<1><<<gP, blk>>>(ctx, Wo, bo, t2, BSn, Dn, Dn);
    // x1 = LN(x + attn_out)
    add_ln<<<BSn, blk>>>(x, t2, ln1g, ln1b, x1);

    // FFN
    sgemm<2><<<gF1, blk>>>(x1, W1, b1, ff, BSn, DFFn, Dn);
    sgemm<1><<<gP,  blk>>>(ff, W2, b2, t2, BSn, Dn, DFFn);

    // x2 = LN(x1 + ff_out)
    add_ln<<<BSn, blk>>>(x1, t2, ln2g, ln2b, out_x2);
}

// round 7
// speedup vs baseline: 1.2327x; 1.2327x over previous
#include <cuda_runtime.h>
#include <cuda_bf16.h>
#include <math.h>
#include <stdint.h>
#include <stddef.h>

// Problem dims (fixed by reference)
constexpr int Bn  = 2;
constexpr int Sn  = 2048;
constexpr int Dn  = 512;
constexpr int Hn  = 8;
constexpr int DKn = 64;
constexpr int DFFn= 2048;
constexpr int BSn = Bn * Sn;          // 4096 token rows
constexpr int QKVN = 3 * Dn;          // 1536 fused qkv width

// ---------------- scratch (device globals; no allocation allowed) ----------
__device__ float g_qkv [BSn * QKVN];
__device__ float g_ctx [BSn * Dn];
__device__ float g_x1  [BSn * Dn];
__device__ float g_t2  [BSn * Dn];
__device__ float g_ff  [BSn * DFFn];
__device__ float g_wt_qkv[QKVN * Dn];  // [1536,512]  rows: Wq^T,Wk^T,Wv^T
__device__ float g_wt_o  [Dn * Dn];    // Wo^T  [512,512]
__device__ float g_wt_1  [DFFn * Dn];  // W1^T  [2048,512]
__device__ float g_wt_2  [Dn * DFFn];  // W2^T  [512,2048]

// ============================ mma.sync helpers =============================
__device__ __forceinline__ void mma_bf16(float* c, const uint32_t* a, const uint32_t* b) {
    asm volatile("mma.sync.aligned.m16n8k16.row.col.f32.bf16.bf16.f32 "
        "{%0,%1,%2,%3}, {%4,%5,%6,%7}, {%8,%9}, {%0,%1,%2,%3};"
        : "+f"(c[0]), "+f"(c[1]), "+f"(c[2]), "+f"(c[3])
        : "r"(a[0]), "r"(a[1]), "r"(a[2]), "r"(a[3]), "r"(b[0]), "r"(b[1]));
}
__device__ __forceinline__ uint32_t pk(__nv_bfloat16 a, __nv_bfloat16 b) {
    return (uint32_t)__bfloat16_as_ushort(a) | ((uint32_t)__bfloat16_as_ushort(b) << 16);
}

// ================= bf16x3-split mma.sync GEMM (128x128 tile) ==============
// C[M,N] = A[M,K] @ Bt^T  (Bt is [N,K] K-major). 8 warps, each 64x32.
// SMEM per k32 stage: A_hi/A_lo/B_hi/B_lo planes, rows padded to 20 b32
// words (80B) -> bank-conflict-free fragment loads.
constexpr int KC      = 32;
constexpr int AST     = 20;                 // b32 words per padded row
constexpr int PLANE_W = 128 * AST;          // 2560 words = 10240 B
constexpr int STAGE_W = 4 * PLANE_W;        // 40960 B
constexpr int GEMM_SMEM = 2 * STAGE_W * 4;  // 81920 B (double buffer)

__device__ __forceinline__ void ldg_tile(const float* __restrict__ A,
                                         const float* __restrict__ Bt,
                                         int row0, int col0, int K, int k0, int tid,
                                         float4* ra, float4* rb) {
    #pragma unroll
    for (int it = 0; it < 4; it++) {
        int idx = tid + it * 256;
        int r = idx >> 3, f = idx & 7;          // 128 rows x 8 float4
        ra[it] = *(const float4*)&A [(size_t)(row0 + r) * K + k0 + f * 4];
        rb[it] = *(const float4*)&Bt[(size_t)(col0 + r) * K + k0 + f * 4];
    }
}
__device__ __forceinline__ void split_sts(uint32_t* hi, uint32_t* lo, int w, float4 v) {
    __nv_bfloat16 h0 = __float2bfloat16_rn(v.x);
    __nv_bfloat16 h1 = __float2bfloat16_rn(v.y);
    __nv_bfloat16 h2 = __float2bfloat16_rn(v.z);
    __nv_bfloat16 h3 = __float2bfloat16_rn(v.w);
    __nv_bfloat16 l0 = __float2bfloat16_rn(v.x - __bfloat162float(h0));
    __nv_bfloat16 l1 = __float2bfloat16_rn(v.y - __bfloat162float(h1));
    __nv_bfloat16 l2 = __float2bfloat16_rn(v.z - __bfloat162float(h2));
    __nv_bfloat16 l3 = __float2bfloat16_rn(v.w - __bfloat162float(h3));
    hi[w]     = pk(h0, h1);
    hi[w + 1] = pk(h2, h3);
    lo[w]     = pk(l0, l1);
    lo[w + 1] = pk(l2, l3);
}
__device__ __forceinline__ void sts_tile(uint32_t* stg, int tid,
                                         const float4* ra, const float4* rb) {
    #pragma unroll
    for (int it = 0; it < 4; it++) {
        int idx = tid + it * 256;
        int r = idx >> 3, f = idx & 7;
        int w = r * AST + f * 2;
        split_sts(stg,              stg + PLANE_W,     w, ra[it]);
        split_sts(stg + 2*PLANE_W,  stg + 3*PLANE_W,   w, rb[it]);
    }
}

// EPI: 0 none, 1 +bias, 2 +bias then exact gelu
template<int EPI>
__global__ __launch_bounds__(256)
void gemm_mma(const float* __restrict__ A, const float* __restrict__ Bt,
              const float* __restrict__ bias, float* __restrict__ C,
              int M, int N, int K)
{
    extern __shared__ uint32_t smw[];
    const int tid  = threadIdx.x;
    const int wid  = tid >> 5, lane = tid & 31;
    const int grp  = lane >> 2, q = lane & 3;
    const int wr   = wid >> 2, wc = wid & 3;     // warp 64x32 tile
    const int row0 = blockIdx.y * 128;
    const int col0 = blockIdx.x * 128;

    float c[4][4][4];
    #pragma unroll
    for (int mt = 0; mt < 4; mt++)
        #pragma unroll
        for (int nt = 0; nt < 4; nt++)
            #pragma unroll
            for (int e = 0; e < 4; e++) c[mt][nt][e] = 0.f;

    const int T = K / KC;
    float4 ra[4], rb[4];

    ldg_tile(A, Bt, row0, col0, K, 0, tid, ra, rb);
    sts_tile(smw, tid, ra, rb);
    __syncthreads();

    for (int i = 0; i < T; i++) {
        const uint32_t* stg = smw + (i & 1) * STAGE_W;
        const uint32_t* Ah = stg;
        const uint32_t* Al = stg + PLANE_W;
        const uint32_t* Bh = stg + 2 * PLANE_W;
        const uint32_t* Bl = stg + 3 * PLANE_W;

        if (i + 1 < T) ldg_tile(A, Bt, row0, col0, K, (i + 1) * KC, tid, ra, rb);

        #pragma unroll
        for (int k16 = 0; k16 < 2; k16++) {
            uint32_t bh[4][2], bl[4][2];
            #pragma unroll
            for (int nt = 0; nt < 4; nt++) {
                int brb = (wc * 32 + nt * 8 + grp) * AST + k16 * 8 + q;
                bh[nt][0] = Bh[brb]; bh[nt][1] = Bh[brb + 4];
                bl[nt][0] = Bl[brb]; bl[nt][1] = Bl[brb + 4];
            }
            #pragma unroll
            for (int mt = 0; mt < 4; mt++) {
                int arb = (wr * 64 + mt * 16 + grp) * AST + k16 * 8 + q;
                uint32_t ah[4], al[4];
                ah[0] = Ah[arb];     ah[1] = Ah[arb + 160];
                ah[2] = Ah[arb + 4]; ah[3] = Ah[arb + 164];
                al[0] = Al[arb];     al[1] = Al[arb + 160];
                al[2] = Al[arb + 4]; al[3] = Al[arb + 164];
                #pragma unroll
                for (int nt = 0; nt < 4; nt++) {
                    mma_bf16(c[mt][nt], ah, bh[nt]);
                    mma_bf16(c[mt][nt], ah, bl[nt]);
                    mma_bf16(c[mt][nt], al, bh[nt]);
                }
            }
        }
        __syncthreads();
        if (i + 1 < T) {
            sts_tile(smw + ((i + 1) & 1) * STAGE_W, tid, ra, rb);
            __syncthreads();
        }
    }

    // epilogue: direct global stores (float2 per c-pair)
    #pragma unroll
    for (int mt = 0; mt < 4; mt++) {
        #pragma unroll
        for (int nt = 0; nt < 4; nt++) {
            int col = col0 + wc * 32 + nt * 8 + 2 * q;
            int r0  = row0 + wr * 64 + mt * 16 + grp;
            float2 v0 = make_float2(c[mt][nt][0], c[mt][nt][1]);
            float2 v1 = make_float2(c[mt][nt][2], c[mt][nt][3]);
            if (EPI >= 1) {
                float b0 = bias[col], b1 = bias[col + 1];
                v0.x += b0; v0.y += b1; v1.x += b0; v1.y += b1;
            }
            if (EPI == 2) {
                v0.x = 0.5f * v0.x * (1.0f + erff(v0.x * 0.70710678118654752f));
                v0.y = 0.5f * v0.y * (1.0f + erff(v0.y * 0.70710678118654752f));
                v1.x = 0.5f * v1.x * (1.0f + erff(v1.x * 0.70710678118654752f));
                v1.y = 0.5f * v1.y * (1.0f + erff(v1.y * 0.70710678118654752f));
            }
            *(float2*)&C[(size_t)r0 * N + col]       = v0;
            *(float2*)&C[(size_t)(r0 + 8) * N + col] = v1;
        }
    }
}

// ============================ weight transpose =============================
// W[K,N] -> Wt[N,K]
__global__ __launch_bounds__(256)
void transpose32(const float* __restrict__ W, float* __restrict__ Wt, int K, int N)
{
    __shared__ float t[32][33];
    int x = blockIdx.x * 32 + threadIdx.x;
    #pragma unroll
    for (int j = 0; j < 4; j++)
        t[threadIdx.y + j * 8][threadIdx.x] =
            W[(size_t)(blockIdx.y * 32 + threadIdx.y + j * 8) * N + x];
    __syncthreads();
    int x2 = blockIdx.y * 32 + threadIdx.x;
    #pragma unroll
    for (int j = 0; j < 4; j++)
        Wt[(size_t)(blockIdx.x * 32 + threadIdx.y + j * 8) * K + x2] =
            t[threadIdx.x][threadIdx.y + j * 8];
}

// ---------------------------------------------------------------------------
// Fused attention: scores -> (+bias, mask) -> softmax -> write attn -> PV.
// q/k/v live in the fused qkv buffer with row stride QKVN.
// ---------------------------------------------------------------------------
constexpr int QT = 16;
constexpr int CN = 256;
constexpr int VSTRIDE = 68;
constexpr int SCORE_F = QT * Sn;
constexpr int QS_F    = DKn * QT;
constexpr int KV_F    = CN * VSTRIDE;
constexpr int ATTN_SMEM_BYTES = (SCORE_F + QS_F + KV_F) * (int)sizeof(float);

__global__ __launch_bounds__(256)
void attn_kernel(const float* __restrict__ qkv, const float* __restrict__ sw,
                 const int* __restrict__ mask, const float* __restrict__ sa,
                 const float* __restrict__ tb,
                 float* __restrict__ attn_out, float* __restrict__ ctx)
{
    extern __shared__ float sm[];
    float* s_sc = sm;
    float* s_q  = sm + SCORE_F;
    float* s_kv = s_q + QS_F;
    __shared__ float s_bias[QT];

    const float* q = qkv;
    const float* k = qkv + Dn;
    const float* v = qkv + 2 * Dn;

    const int tid = threadIdx.x;
    const int qt = blockIdx.x, h = blockIdx.y, b = blockIdx.z;
    const int q0 = qt * QT;

    for (int i = tid; i < QT * DKn; i += 256) {
        int r = i >> 6, d = i & 63;
        s_q[d * QT + r] = q[((size_t)(b*Sn + q0 + r)) * QKVN + h*DKn + d];
    }
    if (tid < QT) {
        const float* swp = sw + ((size_t)(b*Sn) + q0 + tid) * 4;
        const float* sap = sa + h * 4;
        s_bias[tid] = tb[h] + sap[0]*swp[0] + sap[1]*swp[1]
                            + sap[2]*swp[2] + sap[3]*swp[3];
    }

    const int ty = tid >> 6;
    const int tx = tid & 63;
    for (int c0 = 0; c0 < Sn; c0 += CN) {
        __syncthreads();
        #pragma unroll
        for (int it = 0; it < 16; it++) {
            int idx = tid + it * 256;
            int c = idx >> 4, d4 = (idx & 15) << 2;
            float4 kv4 = *(const float4*)&k[((size_t)(b*Sn + c0 + c)) * QKVN + h*DKn + d4];
            s_kv[(d4+0)*CN + c] = kv4.x;
            s_kv[(d4+1)*CN + c] = kv4.y;
            s_kv[(d4+2)*CN + c] = kv4.z;
            s_kv[(d4+3)*CN + c] = kv4.w;
        }
        __syncthreads();
        float acc[4][4];
        #pragma unroll
        for (int i = 0; i < 4; i++)
            #pragma unroll
            for (int j = 0; j < 4; j++) acc[i][j] = 0.f;
        #pragma unroll
        for (int d = 0; d < DKn; d++) {
            float4 a4 = *(const float4*)&s_q[d*QT + 4*ty];
            float4 b4 = *(const float4*)&s_kv[d*CN + 4*tx];
            acc[0][0] += a4.x*b4.x; acc[0][1] += a4.x*b4.y; acc[0][2] += a4.x*b4.z; acc[0][3] += a4.x*b4.w;
            acc[1][0] += a4.y*b4.x; acc[1][1] += a4.y*b4.y; acc[1][2] += a4.y*b4.z; acc[1][3] += a4.y*b4.w;
            acc[2][0] += a4.z*b4.x; acc[2][1] += a4.z*b4.y; acc[2][2] += a4.z*b4.z; acc[2][3] += a4.z*b4.w;
            acc[3][0] += a4.w*b4.x; acc[3][1] += a4.w*b4.y; acc[3][2] += a4.w*b4.z; acc[3][3] += a4.w*b4.w;
        }
        #pragma unroll
        for (int i = 0; i < 4; i++) {
            int rr = 4*ty + i;
            #pragma unroll
            for (int j = 0; j < 4; j++) {
                int cc = c0 + 4*tx + j;
                float val = acc[i][j] * 0.125f + s_bias[rr];
                if (mask[(size_t)(q0 + rr) * Sn + cc] == 0) val = -1e9f;
                s_sc[rr * Sn + cc] = val;
            }
        }
    }
    __syncthreads();

    {
        int w = tid >> 5, lane = tid & 31;
        for (int r = 2*w; r < 2*w + 2; r++) {
            float* sp = s_sc + r * Sn;
            float m = -3.4e38f;
            for (int kk = lane; kk < Sn; kk += 32) m = fmaxf(m, sp[kk]);
            #pragma unroll
            for (int o = 16; o > 0; o >>= 1) m = fmaxf(m, __shfl_xor_sync(0xffffffffu, m, o));
            float s = 0.f;
            for (int kk = lane; kk < Sn; kk += 32) {
                float p = expf(sp[kk] - m);
                sp[kk] = p;
                s += p;
            }
            #pragma unroll
            for (int o = 16; o > 0; o >>= 1) s += __shfl_xor_sync(0xffffffffu, s, o);
            float inv = 1.f / s;
            float* ap = attn_out + ((size_t)((b*Hn + h)*Sn + q0 + r)) * Sn;
            for (int kk = lane; kk < Sn; kk += 32) {
                float p = sp[kk] * inv;
                sp[kk] = p;
                ap[kk] = p;
            }
        }
    }
    __syncthreads();

    const int ry = tid >> 4;
    const int cx = (tid & 15) << 2;
    float o0 = 0.f, o1 = 0.f, o2 = 0.f, o3 = 0.f;
    for (int c0 = 0; c0 < Sn; c0 += CN) {
        #pragma unroll
        for (int it = 0; it < 16; it++) {
            int idx = tid + it * 256;
            int c = idx >> 4, d4 = (idx & 15) << 2;
            float4 vv = *(const float4*)&v[((size_t)(b*Sn + c0 + c)) * QKVN + h*DKn + d4];
            *(float4*)&s_kv[c * VSTRIDE + d4] = vv;
        }
        __syncthreads();
        #pragma unroll 8
        for (int kk = 0; kk < CN; kk++) {
            float a = s_sc[ry * Sn + c0 + kk];
            float4 b4 = *(const float4*)&s_kv[kk * VSTRIDE + cx];
            o0 += a * b4.x; o1 += a * b4.y; o2 += a * b4.z; o3 += a * b4.w;
        }
        __syncthreads();
    }
    float* cp = ctx + ((size_t)(b*Sn + q0 + ry)) * Dn + h*DKn + cx;
    cp[0] = o0; cp[1] = o1; cp[2] = o2; cp[3] = o3;
}

// ---------------------------------------------------------------------------
// out = LayerNorm(a + r) * g + b
// ---------------------------------------------------------------------------
__global__ __launch_bounds__(256)
void add_ln(const float* __restrict__ a, const float* __restrict__ r,
            const float* __restrict__ g, const float* __restrict__ be,
            float* __restrict__ out)
{
    const int row = blockIdx.x, tid = threadIdx.x;
    const float* ap = a + (size_t)row * Dn;
    const float* rp = r + (size_t)row * Dn;
    float v0 = ap[tid]       + rp[tid];
    float v1 = ap[tid + 256] + rp[tid + 256];

    __shared__ float red[8];
    __shared__ float s_mu, s_inv;
    const int w = tid >> 5, lane = tid & 31;

    float s = v0 + v1;
    #pragma unroll
    for (int o = 16; o > 0; o >>= 1) s += __shfl_xor_sync(0xffffffffu, s, o);
    if (lane == 0) red[w] = s;
    __syncthreads();
    if (tid < 32) {
        float t = (tid < 8) ? red[tid] : 0.f;
        #pragma unroll
        for (int o = 4; o > 0; o >>= 1) t += __shfl_xor_sync(0xffffffffu, t, o);
        if (tid == 0) s_mu = t * (1.f / Dn);
    }
    __syncthreads();
    float mu = s_mu;
    float d0 = v0 - mu, d1 = v1 - mu;

    float qv = d0*d0 + d1*d1;
    #pragma unroll
    for (int o = 16; o > 0; o >>= 1) qv += __shfl_xor_sync(0xffffffffu, qv, o);
    __syncthreads();
    if (lane == 0) red[w] = qv;
    __syncthreads();
    if (tid < 32) {
        float t = (tid < 8) ? red[tid] : 0.f;
        #pragma unroll
        for (int o = 4; o > 0; o >>= 1) t += __shfl_xor_sync(0xffffffffu, t, o);
        if (tid == 0) s_inv = rsqrtf(t * (1.f / Dn) + 1e-6f);
    }
    __syncthreads();
    float inv = s_inv;
    float* op = out + (size_t)row * Dn;
    op[tid]       = d0 * inv * g[tid]       + be[tid];
    op[tid + 256] = d1 * inv * g[tid + 256] + be[tid + 256];
}

// ---------------------------------------------------------------------------
extern "C" void kernel_launch(void* const* d_in, const int* in_sizes, int n_in,
                              void* d_out, int out_size)
{
    const float* x    = (const float*)d_in[0];
    const float* sw   = (const float*)d_in[1];
    const int*   mask = (const int*)  d_in[2];
    const float* Wq   = (const float*)d_in[3];
    const float* Wk   = (const float*)d_in[4];
    const float* Wv   = (const float*)d_in[5];
    const float* Wo   = (const float*)d_in[6];
    const float* bo   = (const float*)d_in[7];
    const float* sa   = (const float*)d_in[8];
    const float* tb   = (const float*)d_in[9];
    const float* ln1g = (const float*)d_in[10];
    const float* ln1b = (const float*)d_in[11];
    const float* ln2g = (const float*)d_in[12];
    const float* ln2b = (const float*)d_in[13];
    const float* W1   = (const float*)d_in[14];
    const float* b1   = (const float*)d_in[15];
    const float* W2   = (const float*)d_in[16];
    const float* b2   = (const float*)d_in[17];

    float* out_x2   = (float*)d_out;
    float* out_attn = (float*)d_out + (size_t)BSn * Dn;

    float *qkv, *ctx, *x1, *t2, *ff, *wt_qkv, *wt_o, *wt_1, *wt_2;
    cudaGetSymbolAddress((void**)&qkv,    g_qkv);
    cudaGetSymbolAddress((void**)&ctx,    g_ctx);
    cudaGetSymbolAddress((void**)&x1,     g_x1);
    cudaGetSymbolAddress((void**)&t2,     g_t2);
    cudaGetSymbolAddress((void**)&ff,     g_ff);
    cudaGetSymbolAddress((void**)&wt_qkv, g_wt_qkv);
    cudaGetSymbolAddress((void**)&wt_o,   g_wt_o);
    cudaGetSymbolAddress((void**)&wt_1,   g_wt_1);
    cudaGetSymbolAddress((void**)&wt_2,   g_wt_2);

    cudaFuncSetAttribute(attn_kernel,
                         cudaFuncAttributeMaxDynamicSharedMemorySize, ATTN_SMEM_BYTES);
    cudaFuncSetAttribute(gemm_mma<0>,
                         cudaFuncAttributeMaxDynamicSharedMemorySize, GEMM_SMEM);
    cudaFuncSetAttribute(gemm_mma<1>,
                         cudaFuncAttributeMaxDynamicSharedMemorySize, GEMM_SMEM);
    cudaFuncSetAttribute(gemm_mma<2>,
                         cudaFuncAttributeMaxDynamicSharedMemorySize, GEMM_SMEM);

    dim3 tb8(32, 8);
    // weight transposes: W[K,N] -> Wt[N,K]
    transpose32<<<dim3(Dn/32,  Dn/32),  tb8>>>(Wq, wt_qkv,              Dn, Dn);
    transpose32<<<dim3(Dn/32,  Dn/32),  tb8>>>(Wk, wt_qkv + Dn*Dn,      Dn, Dn);
    transpose32<<<dim3(Dn/32,  Dn/32),  tb8>>>(Wv, wt_qkv + 2*Dn*Dn,    Dn, Dn);
    transpose32<<<dim3(Dn/32,  Dn/32),  tb8>>>(Wo, wt_o,                Dn, Dn);
    transpose32<<<dim3(DFFn/32, Dn/32), tb8>>>(W1, wt_1,                Dn, DFFn);
    transpose32<<<dim3(Dn/32, DFFn/32), tb8>>>(W2, wt_2,                DFFn, Dn);

    dim3 blk(256);

    // fused QKV projection: [4096,512] @ [512,1536]
    gemm_mma<0><<<dim3(QKVN/128, BSn/128), blk, GEMM_SMEM>>>(
        x, wt_qkv, nullptr, qkv, BSn, QKVN, Dn);

    // fused attention
    attn_kernel<<<dim3(Sn / QT, Hn, Bn), blk, ATTN_SMEM_BYTES>>>(
        qkv, sw, mask, sa, tb, out_attn, ctx);

    // output projection + bias
    gemm_mma<1><<<dim3(Dn/128, BSn/128), blk, GEMM_SMEM>>>(
        ctx, wt_o, bo, t2, BSn, Dn, Dn);
    add_ln<<<BSn, blk>>>(x, t2, ln1g, ln1b, x1);

    // FFN
    gemm_mma<2><<<dim3(DFFn/128, BSn/128), blk, GEMM_SMEM>>>(
        x1, wt_1, b1, ff, BSn, DFFn, Dn);
    gemm_mma<1><<<dim3(Dn/128, BSn/128), blk, GEMM_SMEM>>>(
        ff, wt_2, b2, t2, BSn, Dn, DFFn);

    add_ln<<<BSn, blk>>>(x1, t2, ln2g, ln2b, out_x2);
}

// round 9
// speedup vs baseline: 3.2939x; 2.6720x over previous
#include <cuda_runtime.h>
#include <cuda_bf16.h>
#include <math.h>
#include <stdint.h>
#include <stddef.h>

// Problem dims (fixed by reference)
constexpr int Bn  = 2;
constexpr int Sn  = 2048;
constexpr int Dn  = 512;
constexpr int Hn  = 8;
constexpr int DKn = 64;
constexpr int DFFn= 2048;
constexpr int BSn = Bn * Sn;          // 4096 token rows
constexpr int QKVN = 3 * Dn;          // 1536 fused qkv width
constexpr int BHn = Bn * Hn;          // 16 batched heads

// ---------------- scratch (device globals; no allocation allowed) ----------
__device__ float g_qkv [BSn * QKVN];
__device__ float g_ctx [BSn * Dn];
__device__ float g_x1  [BSn * Dn];
__device__ float g_t2  [BSn * Dn];
__device__ float g_ff  [BSn * DFFn];
// bf16 hi/lo weight planes (K-major, [N,K])
__device__ __nv_bfloat16 g_wqkv_h[QKVN * Dn], g_wqkv_l[QKVN * Dn];
__device__ __nv_bfloat16 g_wo_h  [Dn * Dn],   g_wo_l  [Dn * Dn];
__device__ __nv_bfloat16 g_w1_h  [DFFn * Dn], g_w1_l  [DFFn * Dn];
__device__ __nv_bfloat16 g_w2_h  [Dn * DFFn], g_w2_l  [Dn * DFFn];
// V transposed per (b,h): [bh][64][Sn] bf16 hi/lo
__device__ __nv_bfloat16 g_vt_h[BHn * DKn * Sn], g_vt_l[BHn * DKn * Sn];

// ============================ mma.sync helpers =============================
__device__ __forceinline__ void mma_bf16(float* c, const uint32_t* a, const uint32_t* b) {
    asm volatile("mma.sync.aligned.m16n8k16.row.col.f32.bf16.bf16.f32 "
        "{%0,%1,%2,%3}, {%4,%5,%6,%7}, {%8,%9}, {%0,%1,%2,%3};"
        : "+f"(c[0]), "+f"(c[1]), "+f"(c[2]), "+f"(c[3])
        : "r"(a[0]), "r"(a[1]), "r"(a[2]), "r"(a[3]), "r"(b[0]), "r"(b[1]));
}
__device__ __forceinline__ uint32_t pk(__nv_bfloat16 a, __nv_bfloat16 b) {
    return (uint32_t)__bfloat16_as_ushort(a) | ((uint32_t)__bfloat16_as_ushort(b) << 16);
}
__device__ __forceinline__ void split_words(float4 v, uint32_t& w0, uint32_t& w1,
                                            uint32_t& l0, uint32_t& l1) {
    __nv_bfloat16 h0 = __float2bfloat16_rn(v.x);
    __nv_bfloat16 h1 = __float2bfloat16_rn(v.y);
    __nv_bfloat16 h2 = __float2bfloat16_rn(v.z);
    __nv_bfloat16 h3 = __float2bfloat16_rn(v.w);
    w0 = pk(h0, h1); w1 = pk(h2, h3);
    l0 = pk(__float2bfloat16_rn(v.x - __bfloat162float(h0)),
            __float2bfloat16_rn(v.y - __bfloat162float(h1)));
    l1 = pk(__float2bfloat16_rn(v.z - __bfloat162float(h2)),
            __float2bfloat16_rn(v.w - __bfloat162float(h3)));
}

// ================= dense GEMM: fp32 A x pre-split bf16 B ===================
// C[M,N] = A[M,K] @ Bt^T. Bt given as bf16 hi/lo planes [N,K] K-major.
// 128x128 CTA tile, 8 warps of 64x32, KC=32 double-buffered.
constexpr int KC      = 32;
constexpr int AST     = 20;                 // padded b32 words per row
constexpr int PLANE_W = 128 * AST;          // 2560 words
constexpr int STAGE_W = 4 * PLANE_W;
constexpr int GEMM_SMEM = 2 * STAGE_W * 4;  // 81920 B

__device__ __forceinline__ void g_ldg(const float* __restrict__ A,
                                      const __nv_bfloat16* __restrict__ Bh_,
                                      const __nv_bfloat16* __restrict__ Bl_,
                                      int row0, int col0, int K, int k0, int tid,
                                      float4* ra, uint4* rbh, uint4* rbl) {
    #pragma unroll
    for (int it = 0; it < 4; it++) {
        int idx = tid + it * 256;
        int r = idx >> 3, f = idx & 7;
        ra[it] = *(const float4*)&A[(size_t)(row0 + r) * K + k0 + f * 4];
    }
    #pragma unroll
    for (int it = 0; it < 2; it++) {
        int idx = tid + it * 256;
        int r = idx >> 2, f = idx & 3;
        rbh[it] = *(const uint4*)&Bh_[(size_t)(col0 + r) * K + k0 + f * 8];
        rbl[it] = *(const uint4*)&Bl_[(size_t)(col0 + r) * K + k0 + f * 8];
    }
}
__device__ __forceinline__ void g_sts(uint32_t* stg, int tid,
                                      const float4* ra, const uint4* rbh, const uint4* rbl) {
    #pragma unroll
    for (int it = 0; it < 4; it++) {
        int idx = tid + it * 256;
        int r = idx >> 3, f = idx & 7;
        int w = r * AST + f * 2;
        uint32_t h0, h1, l0, l1;
        split_words(ra[it], h0, h1, l0, l1);
        stg[w] = h0; stg[w + 1] = h1;
        stg[PLANE_W + w] = l0; stg[PLANE_W + w + 1] = l1;
    }
    #pragma unroll
    for (int it = 0; it < 2; it++) {
        int idx = tid + it * 256;
        int r = idx >> 2, f = idx & 3;
        int w = r * AST + f * 4;
        *(uint4*)&stg[2 * PLANE_W + w] = rbh[it];
        *(uint4*)&stg[3 * PLANE_W + w] = rbl[it];
    }
}

// EPI: 0 none, 1 +bias, 2 +bias then exact gelu
template<int EPI>
__global__ __launch_bounds__(256)
void gemm_mma(const float* __restrict__ A,
              const __nv_bfloat16* __restrict__ Bth, const __nv_bfloat16* __restrict__ Btl,
              const float* __restrict__ bias, float* __restrict__ C,
              int M, int N, int K)
{
    extern __shared__ uint32_t smw[];
    const int tid  = threadIdx.x;
    const int wid  = tid >> 5, lane = tid & 31;
    const int grp  = lane >> 2, q = lane & 3;
    const int wr   = wid >> 2, wc = wid & 3;
    const int row0 = blockIdx.y * 128;
    const int col0 = blockIdx.x * 128;

    float c[4][4][4];
    #pragma unroll
    for (int mt = 0; mt < 4; mt++)
        #pragma unroll
        for (int nt = 0; nt < 4; nt++)
            #pragma unroll
            for (int e = 0; e < 4; e++) c[mt][nt][e] = 0.f;

    const int T = K / KC;
    float4 ra[4]; uint4 rbh[2], rbl[2];

    g_ldg(A, Bth, Btl, row0, col0, K, 0, tid, ra, rbh, rbl);
    g_sts(smw, tid, ra, rbh, rbl);
    __syncthreads();

    for (int i = 0; i < T; i++) {
        const uint32_t* stg = smw + (i & 1) * STAGE_W;
        const uint32_t* Ah = stg;
        const uint32_t* Al = stg + PLANE_W;
        const uint32_t* Bh = stg + 2 * PLANE_W;
        const uint32_t* Bl = stg + 3 * PLANE_W;

        if (i + 1 < T) g_ldg(A, Bth, Btl, row0, col0, K, (i + 1) * KC, tid, ra, rbh, rbl);

        #pragma unroll
        for (int k16 = 0; k16 < 2; k16++) {
            uint32_t bh[4][2], bl[4][2];
            #pragma unroll
            for (int nt = 0; nt < 4; nt++) {
                int brb = (wc * 32 + nt * 8 + grp) * AST + k16 * 8 + q;
                bh[nt][0] = Bh[brb]; bh[nt][1] = Bh[brb + 4];
                bl[nt][0] = Bl[brb]; bl[nt][1] = Bl[brb + 4];
            }
            #pragma unroll
            for (int mt = 0; mt < 4; mt++) {
                int arb = (wr * 64 + mt * 16 + grp) * AST + k16 * 8 + q;
                uint32_t ah[4], al[4];
                ah[0] = Ah[arb];     ah[1] = Ah[arb + 160];
                ah[2] = Ah[arb + 4]; ah[3] = Ah[arb + 164];
                al[0] = Al[arb];     al[1] = Al[arb + 160];
                al[2] = Al[arb + 4]; al[3] = Al[arb + 164];
                #pragma unroll
                for (int nt = 0; nt < 4; nt++) {
                    mma_bf16(c[mt][nt], ah, bh[nt]);
                    mma_bf16(c[mt][nt], ah, bl[nt]);
                    mma_bf16(c[mt][nt], al, bh[nt]);
                }
            }
        }
        __syncthreads();
        if (i + 1 < T) {
            g_sts(smw + ((i + 1) & 1) * STAGE_W, tid, ra, rbh, rbl);
            __syncthreads();
        }
    }

    #pragma unroll
    for (int mt = 0; mt < 4; mt++) {
        #pragma unroll
        for (int nt = 0; nt < 4; nt++) {
            int col = col0 + wc * 32 + nt * 8 + 2 * q;
            int r0  = row0 + wr * 64 + mt * 16 + grp;
            float2 v0 = make_float2(c[mt][nt][0], c[mt][nt][1]);
            float2 v1 = make_float2(c[mt][nt][2], c[mt][nt][3]);
            if (EPI >= 1) {
                float b0 = bias[col], b1 = bias[col + 1];
                v0.x += b0; v0.y += b1; v1.x += b0; v1.y += b1;
            }
            if (EPI == 2) {
                v0.x = 0.5f * v0.x * (1.0f + erff(v0.x * 0.70710678118654752f));
                v0.y = 0.5f * v0.y * (1.0f + erff(v0.y * 0.70710678118654752f));
                v1.x = 0.5f * v1.x * (1.0f + erff(v1.x * 0.70710678118654752f));
                v1.y = 0.5f * v1.y * (1.0f + erff(v1.y * 0.70710678118654752f));
            }
            *(float2*)&C[(size_t)r0 * N + col]       = v0;
            *(float2*)&C[(size_t)(r0 + 8) * N + col] = v1;
        }
    }
}

// ================= attention phase A: S = Q K^T /8 + bias, mask ============
// Batched over bh. A = Q rows (stride QKVN), B = K rows (stride QKVN). K=64.
__global__ __launch_bounds__(256)
void attn_score(const float* __restrict__ qkv, const float* __restrict__ sw,
                const int* __restrict__ mask, const float* __restrict__ sa,
                const float* __restrict__ tb, float* __restrict__ S_out)
{
    extern __shared__ uint32_t smw[];
    __shared__ float s_rb[128];
    const int tid  = threadIdx.x;
    const int wid  = tid >> 5, lane = tid & 31;
    const int grp  = lane >> 2, q = lane & 3;
    const int wr   = wid >> 2, wc = wid & 3;
    const int bh = blockIdx.z, b = bh >> 3, h = bh & 7;
    const int row0 = blockIdx.y * 128;
    const int col0 = blockIdx.x * 128;

    const float* A = qkv + (size_t)b * Sn * QKVN + h * DKn;            // Q
    const float* Bm = qkv + (size_t)b * Sn * QKVN + Dn + h * DKn;      // K

    if (tid < 128) {
        int row = row0 + tid;
        const float* swp = sw + ((size_t)b * Sn + row) * 4;
        const float* sap = sa + h * 4;
        s_rb[tid] = tb[h] + sap[0]*swp[0] + sap[1]*swp[1]
                          + sap[2]*swp[2] + sap[3]*swp[3];
    }

    float c[4][4][4];
    #pragma unroll
    for (int mt = 0; mt < 4; mt++)
        #pragma unroll
        for (int nt = 0; nt < 4; nt++)
            #pragma unroll
            for (int e = 0; e < 4; e++) c[mt][nt][e] = 0.f;

    // stage both k-chunks (K=64 -> 2 chunks of 32)
    #pragma unroll
    for (int s = 0; s < 2; s++) {
        float4 ra[4], rb[4];
        #pragma unroll
        for (int it = 0; it < 4; it++) {
            int idx = tid + it * 256;
            int r = idx >> 3, f = idx & 7;
            ra[it] = *(const float4*)&A [(size_t)(row0 + r) * QKVN + s * 32 + f * 4];
            rb[it] = *(const float4*)&Bm[(size_t)(col0 + r) * QKVN + s * 32 + f * 4];
        }
        uint32_t* stg = smw + s * STAGE_W;
        #pragma unroll
        for (int it = 0; it < 4; it++) {
            int idx = tid + it * 256;
            int r = idx >> 3, f = idx & 7;
            int w = r * AST + f * 2;
            uint32_t h0, h1, l0, l1;
            split_words(ra[it], h0, h1, l0, l1);
            stg[w] = h0; stg[w + 1] = h1;
            stg[PLANE_W + w] = l0; stg[PLANE_W + w + 1] = l1;
            split_words(rb[it], h0, h1, l0, l1);
            stg[2*PLANE_W + w] = h0; stg[2*PLANE_W + w + 1] = h1;
            stg[3*PLANE_W + w] = l0; stg[3*PLANE_W + w + 1] = l1;
        }
    }
    __syncthreads();

    #pragma unroll
    for (int s = 0; s < 2; s++) {
        const uint32_t* stg = smw + s * STAGE_W;
        const uint32_t* Ah = stg;
        const uint32_t* Al = stg + PLANE_W;
        const uint32_t* Bh = stg + 2 * PLANE_W;
        const uint32_t* Bl = stg + 3 * PLANE_W;
        #pragma unroll
        for (int k16 = 0; k16 < 2; k16++) {
            uint32_t bh2[4][2], bl2[4][2];
            #pragma unroll
            for (int nt = 0; nt < 4; nt++) {
                int brb = (wc * 32 + nt * 8 + grp) * AST + k16 * 8 + q;
                bh2[nt][0] = Bh[brb]; bh2[nt][1] = Bh[brb + 4];
                bl2[nt][0] = Bl[brb]; bl2[nt][1] = Bl[brb + 4];
            }
            #pragma unroll
            for (int mt = 0; mt < 4; mt++) {
                int arb = (wr * 64 + mt * 16 + grp) * AST + k16 * 8 + q;
                uint32_t ah[4], al[4];
                ah[0] = Ah[arb];     ah[1] = Ah[arb + 160];
                ah[2] = Ah[arb + 4]; ah[3] = Ah[arb + 164];
                al[0] = Al[arb];     al[1] = Al[arb + 160];
                al[2] = Al[arb + 4]; al[3] = Al[arb + 164];
                #pragma unroll
                for (int nt = 0; nt < 4; nt++) {
                    mma_bf16(c[mt][nt], ah, bh2[nt]);
                    mma_bf16(c[mt][nt], ah, bl2[nt]);
                    mma_bf16(c[mt][nt], al, bh2[nt]);
                }
            }
        }
    }

    float* S = S_out + (size_t)bh * Sn * Sn;
    #pragma unroll
    for (int mt = 0; mt < 4; mt++) {
        #pragma unroll
        for (int nt = 0; nt < 4; nt++) {
            int col = col0 + wc * 32 + nt * 8 + 2 * q;
            int r0  = row0 + wr * 64 + mt * 16 + grp;
            #pragma unroll
            for (int half = 0; half < 2; half++) {
                int r = r0 + half * 8;
                float2 v = make_float2(c[mt][nt][2*half], c[mt][nt][2*half + 1]);
                float rb = s_rb[r - row0];
                v.x = v.x * 0.125f + rb;
                v.y = v.y * 0.125f + rb;
                int2 m2 = *(const int2*)&mask[(size_t)r * Sn + col];
                if (m2.x == 0) v.x = -1e9f;
                if (m2.y == 0) v.y = -1e9f;
                *(float2*)&S[(size_t)r * Sn + col] = v;
            }
        }
    }
}

// ================= attention phase B: in-place row softmax =================
__global__ __launch_bounds__(256)
void softmax_rows(float* __restrict__ attn)
{
    const int row = blockIdx.x, tid = threadIdx.x;
    float4* p4 = (float4*)(attn + (size_t)row * Sn);
    float4 u0 = p4[tid], u1 = p4[tid + 256];

    __shared__ float red[8];
    __shared__ float s_val;
    const int w = tid >> 5, lane = tid & 31;

    float m = fmaxf(fmaxf(fmaxf(u0.x, u0.y), fmaxf(u0.z, u0.w)),
                    fmaxf(fmaxf(u1.x, u1.y), fmaxf(u1.z, u1.w)));
    #pragma unroll
    for (int o = 16; o > 0; o >>= 1) m = fmaxf(m, __shfl_xor_sync(0xffffffffu, m, o));
    if (lane == 0) red[w] = m;
    __syncthreads();
    if (tid == 0) {
        float t = red[0];
        #pragma unroll
        for (int i = 1; i < 8; i++) t = fmaxf(t, red[i]);
        s_val = t;
    }
    __syncthreads();
    m = s_val;

    u0.x = expf(u0.x - m); u0.y = expf(u0.y - m);
    u0.z = expf(u0.z - m); u0.w = expf(u0.w - m);
    u1.x = expf(u1.x - m); u1.y = expf(u1.y - m);
    u1.z = expf(u1.z - m); u1.w = expf(u1.w - m);

    float s = u0.x + u0.y + u0.z + u0.w + u1.x + u1.y + u1.z + u1.w;
    #pragma unroll
    for (int o = 16; o > 0; o >>= 1) s += __shfl_xor_sync(0xffffffffu, s, o);
    __syncthreads();
    if (lane == 0) red[w] = s;
    __syncthreads();
    if (tid == 0) {
        float t = 0.f;
        #pragma unroll
        for (int i = 0; i < 8; i++) t += red[i];
        s_val = 1.f / t;
    }
    __syncthreads();
    float inv = s_val;
    u0.x *= inv; u0.y *= inv; u0.z *= inv; u0.w *= inv;
    u1.x *= inv; u1.y *= inv; u1.z *= inv; u1.w *= inv;
    p4[tid] = u0; p4[tid + 256] = u1;
}

// ================= attention phase C: ctx = P @ V ==========================
// Per bh: ctx[Sn,64] = P[Sn,Sn] @ V. B = V^T bf16 planes [64,Sn] K-major.
constexpr int PV_APL   = 128 * AST;            // 2560 words
constexpr int PV_BPL   = 64 * AST;             // 1280 words
constexpr int PV_STAGE = 2 * PV_APL + 2 * PV_BPL;
constexpr int PV_SMEM  = 2 * PV_STAGE * 4;     // 61440 B

__global__ __launch_bounds__(256)
void attn_pv(const float* __restrict__ Pm,
             const __nv_bfloat16* __restrict__ vth, const __nv_bfloat16* __restrict__ vtl,
             float* __restrict__ ctx)
{
    extern __shared__ uint32_t smw[];
    const int tid  = threadIdx.x;
    const int wid  = tid >> 5, lane = tid & 31;
    const int grp  = lane >> 2, q = lane & 3;
    const int bh = blockIdx.y, b = bh >> 3, h = bh & 7;
    const int m0 = blockIdx.x * 128;

    const float* A = Pm + (size_t)bh * Sn * Sn;
    const __nv_bfloat16* Bh_ = vth + (size_t)bh * DKn * Sn;
    const __nv_bfloat16* Bl_ = vtl + (size_t)bh * DKn * Sn;

    float c[8][4];
    #pragma unroll
    for (int nt = 0; nt < 8; nt++)
        #pragma unroll
        for (int e = 0; e < 4; e++) c[nt][e] = 0.f;

    const int T = Sn / KC;   // 64
    float4 ra[4]; uint4 rbh, rbl;

    // ldg lambda-free helpers inline
    {
        #pragma unroll
        for (int it = 0; it < 4; it++) {
            int idx = tid + it * 256;
            int r = idx >> 3, f = idx & 7;
            ra[it] = *(const float4*)&A[(size_t)(m0 + r) * Sn + f * 4];
        }
        int r = tid >> 2, f = tid & 3;
        rbh = *(const uint4*)&Bh_[(size_t)r * Sn + f * 8];
        rbl = *(const uint4*)&Bl_[(size_t)r * Sn + f * 8];
        uint32_t* stg = smw;
        #pragma unroll
        for (int it = 0; it < 4; it++) {
            int idx = tid + it * 256;
            int rr = idx >> 3, ff = idx & 7;
            int w = rr * AST + ff * 2;
            uint32_t h0, h1, l0, l1;
            split_words(ra[it], h0, h1, l0, l1);
            stg[w] = h0; stg[w + 1] = h1;
            stg[PV_APL + w] = l0; stg[PV_APL + w + 1] = l1;
        }
        int w = r * AST + f * 4;
        *(uint4*)&stg[2 * PV_APL + w] = rbh;
        *(uint4*)&stg[2 * PV_APL + PV_BPL + w] = rbl;
    }
    __syncthreads();

    for (int i = 0; i < T; i++) {
        const uint32_t* stg = smw + (i & 1) * PV_STAGE;
        const uint32_t* Ah = stg;
        const uint32_t* Al = stg + PV_APL;
        const uint32_t* Bhp = stg + 2 * PV_APL;
        const uint32_t* Blp = stg + 2 * PV_APL + PV_BPL;

        if (i + 1 < T) {
            int k0 = (i + 1) * KC;
            #pragma unroll
            for (int it = 0; it < 4; it++) {
                int idx = tid + it * 256;
                int r = idx >> 3, f = idx & 7;
                ra[it] = *(const float4*)&A[(size_t)(m0 + r) * Sn + k0 + f * 4];
            }
            int r = tid >> 2, f = tid & 3;
            rbh = *(const uint4*)&Bh_[(size_t)r * Sn + k0 + f * 8];
            rbl = *(const uint4*)&Bl_[(size_t)r * Sn + k0 + f * 8];
        }

        #pragma unroll
        for (int k16 = 0; k16 < 2; k16++) {
            int arb = (wid * 16 + grp) * AST + k16 * 8 + q;
            uint32_t ah[4], al[4];
            ah[0] = Ah[arb];     ah[1] = Ah[arb + 160];
            ah[2] = Ah[arb + 4]; ah[3] = Ah[arb + 164];
            al[0] = Al[arb];     al[1] = Al[arb + 160];
            al[2] = Al[arb + 4]; al[3] = Al[arb + 164];
            #pragma unroll
            for (int nt = 0; nt < 8; nt++) {
                int brb = (nt * 8 + grp) * AST + k16 * 8 + q;
                uint32_t bh2[2], bl2[2];
                bh2[0] = Bhp[brb]; bh2[1] = Bhp[brb + 4];
                bl2[0] = Blp[brb]; bl2[1] = Blp[brb + 4];
                mma_bf16(c[nt], ah, bh2);
                mma_bf16(c[nt], ah, bl2);
                mma_bf16(c[nt], al, bh2);
            }
        }
        __syncthreads();
        if (i + 1 < T) {
            uint32_t* stg2 = smw + ((i + 1) & 1) * PV_STAGE;
            #pragma unroll
            for (int it = 0; it < 4; it++) {
                int idx = tid + it * 256;
                int rr = idx >> 3, ff = idx & 7;
                int w = rr * AST + ff * 2;
                uint32_t h0, h1, l0, l1;
                split_words(ra[it], h0, h1, l0, l1);
                stg2[w] = h0; stg2[w + 1] = h1;
                stg2[PV_APL + w] = l0; stg2[PV_APL + w + 1] = l1;
            }
            int r = tid >> 2, f = tid & 3;
            int w = r * AST + f * 4;
            *(uint4*)&stg2[2 * PV_APL + w] = rbh;
            *(uint4*)&stg2[2 * PV_APL + PV_BPL + w] = rbl;
            __syncthreads();
        }
    }

    #pragma unroll
    for (int nt = 0; nt < 8; nt++) {
        int col = h * DKn + nt * 8 + 2 * q;
        int r0  = m0 + wid * 16 + grp;
        *(float2*)&ctx[(size_t)(b * Sn + r0) * Dn + col]     = make_float2(c[nt][0], c[nt][1]);
        *(float2*)&ctx[(size_t)(b * Sn + r0 + 8) * Dn + col] = make_float2(c[nt][2], c[nt][3]);
    }
}

// ============================ weight transpose (-> bf16 hi/lo) =============
// W[K,N] -> Wt[N,K] bf16 hi/lo planes
__global__ __launch_bounds__(256)
void transpose_w(const float* __restrict__ W, __nv_bfloat16* __restrict__ Wth,
                 __nv_bfloat16* __restrict__ Wtl, int K, int N)
{
    __shared__ float t[32][33];
    int x = blockIdx.x * 32 + threadIdx.x;
    #pragma unroll
    for (int j = 0; j < 4; j++)
        t[threadIdx.y + j * 8][threadIdx.x] =
            W[(size_t)(blockIdx.y * 32 + threadIdx.y + j * 8) * N + x];
    __syncthreads();
    int x2 = blockIdx.y * 32 + threadIdx.x;
    #pragma unroll
    for (int j = 0; j < 4; j++) {
        float v = t[threadIdx.x][threadIdx.y + j * 8];
        __nv_bfloat16 hi = __float2bfloat16_rn(v);
        size_t o = (size_t)(blockIdx.x * 32 + threadIdx.y + j * 8) * K + x2;
        Wth[o] = hi;
        Wtl[o] = __float2bfloat16_rn(v - __bfloat162float(hi));
    }
}

// V slice of qkv -> vt[bh][64][Sn] bf16 hi/lo
__global__ __launch_bounds__(256)
void transpose_v(const float* __restrict__ qkv, __nv_bfloat16* __restrict__ vth,
                 __nv_bfloat16* __restrict__ vtl)
{
    __shared__ float t[32][33];
    const int bh = blockIdx.z, b = bh >> 3, h = bh & 7;
    const int s0 = blockIdx.x * 32;       // 64 tiles
    const int d0 = blockIdx.y * 32;       // 2 tiles
    const int vcol = 2 * Dn + h * DKn;
    #pragma unroll
    for (int j = 0; j < 4; j++)
        t[threadIdx.y + j * 8][threadIdx.x] =
            qkv[(size_t)(b * Sn + s0 + threadIdx.y + j * 8) * QKVN + vcol + d0 + threadIdx.x];
    __syncthreads();
    #pragma unroll
    for (int j = 0; j < 4; j++) {
        float v = t[threadIdx.x][threadIdx.y + j * 8];
        __nv_bfloat16 hi = __float2bfloat16_rn(v);
        size_t o = ((size_t)bh * DKn + d0 + threadIdx.y + j * 8) * Sn + s0 + threadIdx.x;
        vth[o] = hi;
        vtl[o] = __float2bfloat16_rn(v - __bfloat162float(hi));
    }
}

// ---------------------------------------------------------------------------
// out = LayerNorm(a + r) * g + b
// ---------------------------------------------------------------------------
__global__ __launch_bounds__(256)
void add_ln(const float* __restrict__ a, const float* __restrict__ r,
            const float* __restrict__ g, const float* __restrict__ be,
            float* __restrict__ out)
{
    const int row = blockIdx.x, tid = threadIdx.x;
    const float* ap = a + (size_t)row * Dn;
    const float* rp = r + (size_t)row * Dn;
    float v0 = ap[tid]       + rp[tid];
    float v1 = ap[tid + 256] + rp[tid + 256];

    __shared__ float red[8];
    __shared__ float s_mu, s_inv;
    const int w = tid >> 5, lane = tid & 31;

    float s = v0 + v1;
    #pragma unroll
    for (int o = 16; o > 0; o >>= 1) s += __shfl_xor_sync(0xffffffffu, s, o);
    if (lane == 0) red[w] = s;
    __syncthreads();
    if (tid < 32) {
        float t = (tid < 8) ? red[tid] : 0.f;
        #pragma unroll
        for (int o = 4; o > 0; o >>= 1) t += __shfl_xor_sync(0xffffffffu, t, o);
        if (tid == 0) s_mu = t * (1.f / Dn);
    }
    __syncthreads();
    float mu = s_mu;
    float d0 = v0 - mu, d1 = v1 - mu;

    float qv = d0*d0 + d1*d1;
    #pragma unroll
    for (int o = 16; o > 0; o >>= 1) qv += __shfl_xor_sync(0xffffffffu, qv, o);
    __syncthreads();
    if (lane == 0) red[w] = qv;
    __syncthreads();
    if (tid < 32) {
        float t = (tid < 8) ? red[tid] : 0.f;
        #pragma unroll
        for (int o = 4; o > 0; o >>= 1) t += __shfl_xor_sync(0xffffffffu, t, o);
        if (tid == 0) s_inv = rsqrtf(t * (1.f / Dn) + 1e-6f);
    }
    __syncthreads();
    float inv = s_inv;
    float* op = out + (size_t)row * Dn;
    op[tid]       = d0 * inv * g[tid]       + be[tid];
    op[tid + 256] = d1 * inv * g[tid + 256] + be[tid + 256];
}

// ---------------------------------------------------------------------------
extern "C" void kernel_launch(void* const* d_in, const int* in_sizes, int n_in,
                              void* d_out, int out_size)
{
    const float* x    = (const float*)d_in[0];
    const float* sw   = (const float*)d_in[1];
    const int*   mask = (const int*)  d_in[2];
    const float* Wq   = (const float*)d_in[3];
    const float* Wk   = (const float*)d_in[4];
    const float* Wv   = (const float*)d_in[5];
    const float* Wo   = (const float*)d_in[6];
    const float* bo   = (const float*)d_in[7];
    const float* sa   = (const float*)d_in[8];
    const float* tb   = (const float*)d_in[9];
    const float* ln1g = (const float*)d_in[10];
    const float* ln1b = (const float*)d_in[11];
    const float* ln2g = (const float*)d_in[12];
    const float* ln2b = (const float*)d_in[13];
    const float* W1   = (const float*)d_in[14];
    const float* b1   = (const float*)d_in[15];
    const float* W2   = (const float*)d_in[16];
    const float* b2   = (const float*)d_in[17];

    float* out_x2   = (float*)d_out;
    float* out_attn = (float*)d_out + (size_t)BSn * Dn;

    float *qkv, *ctx, *x1, *t2, *ff;
    __nv_bfloat16 *wqkv_h, *wqkv_l, *wo_h, *wo_l, *w1_h, *w1_l, *w2_h, *w2_l, *vth, *vtl;
    cudaGetSymbolAddress((void**)&qkv,    g_qkv);
    cudaGetSymbolAddress((void**)&ctx,    g_ctx);
    cudaGetSymbolAddress((void**)&x1,     g_x1);
    cudaGetSymbolAddress((void**)&t2,     g_t2);
    cudaGetSymbolAddress((void**)&ff,     g_ff);
    cudaGetSymbolAddress((void**)&wqkv_h, g_wqkv_h);
    cudaGetSymbolAddress((void**)&wqkv_l, g_wqkv_l);
    cudaGetSymbolAddress((void**)&wo_h,   g_wo_h);
    cudaGetSymbolAddress((void**)&wo_l,   g_wo_l);
    cudaGetSymbolAddress((void**)&w1_h,   g_w1_h);
    cudaGetSymbolAddress((void**)&w1_l,   g_w1_l);
    cudaGetSymbolAddress((void**)&w2_h,   g_w2_h);
    cudaGetSymbolAddress((void**)&w2_l,   g_w2_l);
    cudaGetSymbolAddress((void**)&vth,    g_vt_h);
    cudaGetSymbolAddress((void**)&vtl,    g_vt_l);

    cudaFuncSetAttribute(gemm_mma<0>, cudaFuncAttributeMaxDynamicSharedMemorySize, GEMM_SMEM);
    cudaFuncSetAttribute(gemm_mma<1>, cudaFuncAttributeMaxDynamicSharedMemorySize, GEMM_SMEM);
    cudaFuncSetAttribute(gemm_mma<2>, cudaFuncAttributeMaxDynamicSharedMemorySize, GEMM_SMEM);
    cudaFuncSetAttribute(attn_score,  cudaFuncAttributeMaxDynamicSharedMemorySize, GEMM_SMEM);
    cudaFuncSetAttribute(attn_pv,     cudaFuncAttributeMaxDynamicSharedMemorySize, PV_SMEM);

    dim3 tb8(32, 8);
    transpose_w<<<dim3(Dn/32,  Dn/32),  tb8>>>(Wq, wqkv_h,            wqkv_l,            Dn, Dn);
    transpose_w<<<dim3(Dn/32,  Dn/32),  tb8>>>(Wk, wqkv_h + Dn*Dn,    wqkv_l + Dn*Dn,    Dn, Dn);
    transpose_w<<<dim3(Dn/32,  Dn/32),  tb8>>>(Wv, wqkv_h + 2*Dn*Dn,  wqkv_l + 2*Dn*Dn,  Dn, Dn);
    transpose_w<<<dim3(Dn/32,  Dn/32),  tb8>>>(Wo, wo_h, wo_l, Dn, Dn);
    transpose_w<<<dim3(DFFn/32, Dn/32), tb8>>>(W1, w1_h, w1_l, Dn, DFFn);
    transpose_w<<<dim3(Dn/32, DFFn/32), tb8>>>(W2, w2_h, w2_l, DFFn, Dn);

    dim3 blk(256);

    // fused QKV projection
    gemm_mma<0><<<dim3(QKVN/128, BSn/128), blk, GEMM_SMEM>>>(
        x, wqkv_h, wqkv_l, nullptr, qkv, BSn, QKVN, Dn);

    // V transpose for PV phase
    transpose_v<<<dim3(Sn/32, DKn/32, BHn), tb8>>>(qkv, vth, vtl);

    // attention: scores -> softmax (in place in d_out) -> PV
    attn_score<<<dim3(Sn/128, Sn/128, BHn), blk, GEMM_SMEM>>>(
        qkv, sw, mask, sa, tb, out_attn);
    softmax_rows<<<BHn * Sn, blk>>>(out_attn);
    attn_pv<<<dim3(Sn/128, BHn), blk, PV_SMEM>>>(out_attn, vth, vtl, ctx);

    // output projection + bias
    gemm_mma<1><<<dim3(Dn/128, BSn/128), blk, GEMM_SMEM>>>(
        ctx, wo_h, wo_l, bo, t2, BSn, Dn, Dn);
    add_ln<<<BSn, blk>>>(x, t2, ln1g, ln1b, x1);

    // FFN
    gemm_mma<2><<<dim3(DFFn/128, BSn/128), blk, GEMM_SMEM>>>(
        x1, w1_h, w1_l, b1, ff, BSn, DFFn, Dn);
    gemm_mma<1><<<dim3(Dn/128, BSn/128), blk, GEMM_SMEM>>>(
        ff, w2_h, w2_l, b2, t2, BSn, Dn, DFFn);

    add_ln<<<BSn, blk>>>(x1, t2, ln2g, ln2b, out_x2);
}

// round 12
// speedup vs baseline: 3.7540x; 1.1397x over previous
#include <cuda_runtime.h>
#include <cuda_bf16.h>
#include <math.h>
#include <stdint.h>
#include <stddef.h>

// Problem dims (fixed by reference)
constexpr int Bn  = 2;
constexpr int Sn  = 2048;
constexpr int Dn  = 512;
constexpr int Hn  = 8;
constexpr int DKn = 64;
constexpr int DFFn= 2048;
constexpr int BSn = Bn * Sn;          // 4096 token rows
constexpr int QKVN = 3 * Dn;          // 1536 fused qkv width
constexpr int BHn = Bn * Hn;          // 16 batched heads

// ---------------- scratch (device globals; no allocation allowed) ----------
__device__ float g_x1  [BSn * Dn];
__device__ float g_t2  [BSn * Dn];
__device__ float g_rowsum[BHn * Sn];
// activation bf16 hi/lo planes
__device__ __nv_bfloat16 g_x_h  [BSn * Dn],   g_x_l  [BSn * Dn];
__device__ __nv_bfloat16 g_qkv_h[BSn * QKVN], g_qkv_l[BSn * QKVN];
__device__ __nv_bfloat16 g_ctx_h[BSn * Dn],   g_ctx_l[BSn * Dn];
__device__ __nv_bfloat16 g_x1_h [BSn * Dn],   g_x1_l [BSn * Dn];
__device__ __nv_bfloat16 g_ff_h [BSn * DFFn], g_ff_l [BSn * DFFn];
// weight bf16 hi/lo planes (K-major, [N,K])
__device__ __nv_bfloat16 g_wqkv_h[QKVN * Dn], g_wqkv_l[QKVN * Dn];
__device__ __nv_bfloat16 g_wo_h  [Dn * Dn],   g_wo_l  [Dn * Dn];
__device__ __nv_bfloat16 g_w1_h  [DFFn * Dn], g_w1_l  [DFFn * Dn];
__device__ __nv_bfloat16 g_w2_h  [Dn * DFFn], g_w2_l  [Dn * DFFn];
// V transposed per (b,h): [bh][64][Sn] bf16 hi/lo
__device__ __nv_bfloat16 g_vt_h[BHn * DKn * Sn], g_vt_l[BHn * DKn * Sn];

// ============================ PTX helpers ==================================
__device__ __forceinline__ uint32_t smem_u32(const void* p) {
    uint32_t a;
    asm("{ .reg .u64 t; cvta.to.shared.u64 t, %1; cvt.u32.u64 %0, t; }"
        : "=r"(a) : "l"(p));
    return a;
}
__device__ __forceinline__ void mma_bf16(float* c, const uint32_t* a, const uint32_t* b) {
    asm volatile("mma.sync.aligned.m16n8k16.row.col.f32.bf16.bf16.f32 "
        "{%0,%1,%2,%3}, {%4,%5,%6,%7}, {%8,%9}, {%0,%1,%2,%3};"
        : "+f"(c[0]), "+f"(c[1]), "+f"(c[2]), "+f"(c[3])
        : "r"(a[0]), "r"(a[1]), "r"(a[2]), "r"(a[3]), "r"(b[0]), "r"(b[1]));
}
__device__ __forceinline__ uint32_t pk(__nv_bfloat16 a, __nv_bfloat16 b) {
    return (uint32_t)__bfloat16_as_ushort(a) | ((uint32_t)__bfloat16_as_ushort(b) << 16);
}
__device__ __forceinline__ void split2(float x, float y, uint32_t& hw, uint32_t& lw) {
    __nv_bfloat16 h0 = __float2bfloat16_rn(x);
    __nv_bfloat16 h1 = __float2bfloat16_rn(y);
    hw = pk(h0, h1);
    lw = pk(__float2bfloat16_rn(x - __bfloat162float(h0)),
            __float2bfloat16_rn(y - __bfloat162float(h1)));
}
__device__ __forceinline__ void cpa16(uint32_t dst, const void* src) {
    asm volatile("cp.async.cg.shared.global [%0], [%1], 16;" :: "r"(dst), "l"(src));
}
__device__ __forceinline__ void cpa_commit() {
    asm volatile("cp.async.commit_group;" ::: "memory");
}
template<int N> __device__ __forceinline__ void cpa_wait() {
    asm volatile("cp.async.wait_group %0;" :: "n"(N) : "memory");
}

// ================= shared tiling constants =================================
constexpr int KC      = 32;
constexpr int AST     = 20;                 // padded b32 words per 32-elt row
constexpr int PLANE_W = 128 * AST;          // 2560 words
constexpr int STAGE_W = 4 * PLANE_W;        // Ah, Al, Bh, Bl
constexpr int GEMM_SMEM = 2 * STAGE_W * 4;  // 81920 B

// ================= dense GEMM: pre-split bf16 planes, cp.async =============
// C = A @ Bt^T. A planes [M,K] row-major, Bt planes [N,K] K-major.
// 128x128 CTA tile, 8 warps of 64x32, KC=32, cp.async double buffer.
// EPI: 0 none, 1 +bias, 2 +bias+gelu.  WF: write fp32 C.  WP: write C planes.
template<int EPI, bool WF, bool WP>
__global__ __launch_bounds__(256)
void gemm_mma(const __nv_bfloat16* __restrict__ Ah_, const __nv_bfloat16* __restrict__ Al_,
              const __nv_bfloat16* __restrict__ Bth, const __nv_bfloat16* __restrict__ Btl,
              const float* __restrict__ bias, float* __restrict__ Cf,
              __nv_bfloat16* __restrict__ Ch, __nv_bfloat16* __restrict__ Cl,
              int M, int N, int K)
{
    extern __shared__ uint32_t smw[];
    const uint32_t sbase = smem_u32(smw);
    const int tid  = threadIdx.x;
    const int wid  = tid >> 5, lane = tid & 31;
    const int grp  = lane >> 2, q = lane & 3;
    const int wr   = wid >> 2, wc = wid & 3;
    const int row0 = blockIdx.y * 128;
    const int col0 = blockIdx.x * 128;

    float c[4][4][4];
    #pragma unroll
    for (int mt = 0; mt < 4; mt++)
        #pragma unroll
        for (int nt = 0; nt < 4; nt++)
            #pragma unroll
            for (int e = 0; e < 4; e++) c[mt][nt][e] = 0.f;

    const int T = K / KC;

    auto issue = [&](int i) {
        int k0 = i * KC;
        uint32_t sb = sbase + (uint32_t)((i & 1) * STAGE_W) * 4;
        #pragma unroll
        for (int it = 0; it < 8; it++) {
            int idx = tid + it * 256;
            int plane = idx >> 9, rem = idx & 511;
            int r = rem >> 2, ch = rem & 3;
            const __nv_bfloat16* src;
            if (plane == 0)      src = Ah_ + (size_t)(row0 + r) * K + k0 + ch * 8;
            else if (plane == 1) src = Al_ + (size_t)(row0 + r) * K + k0 + ch * 8;
            else if (plane == 2) src = Bth + (size_t)(col0 + r) * K + k0 + ch * 8;
            else                 src = Btl + (size_t)(col0 + r) * K + k0 + ch * 8;
            cpa16(sb + (uint32_t)(plane * PLANE_W + r * AST + ch * 4) * 4, src);
        }
        cpa_commit();
    };

    issue(0);
    for (int i = 0; i < T; i++) {
        if (i + 1 < T) { issue(i + 1); cpa_wait<1>(); }
        else           { cpa_wait<0>(); }
        __syncthreads();

        const uint32_t* stg = smw + (i & 1) * STAGE_W;
        const uint32_t* Ah = stg;
        const uint32_t* Al = stg + PLANE_W;
        const uint32_t* Bh = stg + 2 * PLANE_W;
        const uint32_t* Bl = stg + 3 * PLANE_W;
        #pragma unroll
        for (int k16 = 0; k16 < 2; k16++) {
            uint32_t bh[4][2], bl[4][2];
            #pragma unroll
            for (int nt = 0; nt < 4; nt++) {
                int brb = (wc * 32 + nt * 8 + grp) * AST + k16 * 8 + q;
                bh[nt][0] = Bh[brb]; bh[nt][1] = Bh[brb + 4];
                bl[nt][0] = Bl[brb]; bl[nt][1] = Bl[brb + 4];
            }
            #pragma unroll
            for (int mt = 0; mt < 4; mt++) {
                int arb = (wr * 64 + mt * 16 + grp) * AST + k16 * 8 + q;
                uint32_t ah[4], al[4];
                ah[0] = Ah[arb];     ah[1] = Ah[arb + 160];
                ah[2] = Ah[arb + 4]; ah[3] = Ah[arb + 164];
                al[0] = Al[arb];     al[1] = Al[arb + 160];
                al[2] = Al[arb + 4]; al[3] = Al[arb + 164];
                #pragma unroll
                for (int nt = 0; nt < 4; nt++) {
                    mma_bf16(c[mt][nt], ah, bh[nt]);
                    mma_bf16(c[mt][nt], ah, bl[nt]);
                    mma_bf16(c[mt][nt], al, bh[nt]);
                }
            }
        }
        __syncthreads();
    }

    #pragma unroll
    for (int mt = 0; mt < 4; mt++) {
        #pragma unroll
        for (int nt = 0; nt < 4; nt++) {
            int col = col0 + wc * 32 + nt * 8 + 2 * q;
            int r0  = row0 + wr * 64 + mt * 16 + grp;
            float2 v0 = make_float2(c[mt][nt][0], c[mt][nt][1]);
            float2 v1 = make_float2(c[mt][nt][2], c[mt][nt][3]);
            if (EPI >= 1) {
                float b0 = bias[col], b1 = bias[col + 1];
                v0.x += b0; v0.y += b1; v1.x += b0; v1.y += b1;
            }
            if (EPI == 2) {
                v0.x = 0.5f * v0.x * (1.0f + erff(v0.x * 0.70710678118654752f));
                v0.y = 0.5f * v0.y * (1.0f + erff(v0.y * 0.70710678118654752f));
                v1.x = 0.5f * v1.x * (1.0f + erff(v1.x * 0.70710678118654752f));
                v1.y = 0.5f * v1.y * (1.0f + erff(v1.y * 0.70710678118654752f));
            }
            if (WF) {
                *(float2*)&Cf[(size_t)r0 * N + col]       = v0;
                *(float2*)&Cf[(size_t)(r0 + 8) * N + col] = v1;
            }
            if (WP) {
                uint32_t hw, lw;
                split2(v0.x, v0.y, hw, lw);
                *(uint32_t*)&Ch[(size_t)r0 * N + col] = hw;
                *(uint32_t*)&Cl[(size_t)r0 * N + col] = lw;
                split2(v1.x, v1.y, hw, lw);
                *(uint32_t*)&Ch[(size_t)(r0 + 8) * N + col] = hw;
                *(uint32_t*)&Cl[(size_t)(r0 + 8) * N + col] = lw;
            }
        }
    }
}

// ================= attention phase A: S = Q K^T /8 + bias, mask, expsum ====
__global__ __launch_bounds__(256)
void attn_score(const __nv_bfloat16* __restrict__ qh, const __nv_bfloat16* __restrict__ ql,
                const float* __restrict__ sw, const int* __restrict__ mask,
                const float* __restrict__ sa, const float* __restrict__ tb,
                float* __restrict__ S_out, float* __restrict__ rowsum)
{
    extern __shared__ uint32_t smw[];
    __shared__ float s_rb[128];
    __shared__ float s_sum[128];
    const uint32_t sbase = smem_u32(smw);
    const int tid  = threadIdx.x;
    const int wid  = tid >> 5, lane = tid & 31;
    const int grp  = lane >> 2, q = lane & 3;
    const int wr   = wid >> 2, wc = wid & 3;
    const int bh = blockIdx.z, b = bh >> 3, h = bh & 7;
    const int row0 = blockIdx.y * 128;
    const int col0 = blockIdx.x * 128;

    const size_t qbase = (size_t)b * Sn * QKVN + h * DKn;        // Q cols
    const size_t kbase = (size_t)b * Sn * QKVN + Dn + h * DKn;   // K cols

    // issue both K-chunks (K=64)
    #pragma unroll
    for (int s = 0; s < 2; s++) {
        int k0 = s * KC;
        uint32_t sb = sbase + (uint32_t)(s * STAGE_W) * 4;
        #pragma unroll
        for (int it = 0; it < 8; it++) {
            int idx = tid + it * 256;
            int plane = idx >> 9, rem = idx & 511;
            int r = rem >> 2, ch = rem & 3;
            const __nv_bfloat16* src;
            if (plane == 0)      src = qh + qbase + (size_t)(row0 + r) * QKVN + k0 + ch * 8;
            else if (plane == 1) src = ql + qbase + (size_t)(row0 + r) * QKVN + k0 + ch * 8;
            else if (plane == 2) src = qh + kbase + (size_t)(col0 + r) * QKVN + k0 + ch * 8;
            else                 src = ql + kbase + (size_t)(col0 + r) * QKVN + k0 + ch * 8;
            cpa16(sb + (uint32_t)(plane * PLANE_W + r * AST + ch * 4) * 4, src);
        }
    }
    cpa_commit();

    if (tid < 128) {
        int row = row0 + tid;
        const float* swp = sw + ((size_t)b * Sn + row) * 4;
        const float* sap = sa + h * 4;
        s_rb[tid] = tb[h] + sap[0]*swp[0] + sap[1]*swp[1]
                          + sap[2]*swp[2] + sap[3]*swp[3];
        s_sum[tid] = 0.f;
    }

    float c[4][4][4];
    #pragma unroll
    for (int mt = 0; mt < 4; mt++)
        #pragma unroll
        for (int nt = 0; nt < 4; nt++)
            #pragma unroll
            for (int e = 0; e < 4; e++) c[mt][nt][e] = 0.f;

    cpa_wait<0>();
    __syncthreads();

    #pragma unroll
    for (int s = 0; s < 2; s++) {
        const uint32_t* stg = smw + s * STAGE_W;
        const uint32_t* Ah = stg;
        const uint32_t* Al = stg + PLANE_W;
        const uint32_t* Bh = stg + 2 * PLANE_W;
        const uint32_t* Bl = stg + 3 * PLANE_W;
        #pragma unroll
        for (int k16 = 0; k16 < 2; k16++) {
            uint32_t bh2[4][2], bl2[4][2];
            #pragma unroll
            for (int nt = 0; nt < 4; nt++) {
                int brb = (wc * 32 + nt * 8 + grp) * AST + k16 * 8 + q;
                bh2[nt][0] = Bh[brb]; bh2[nt][1] = Bh[brb + 4];
                bl2[nt][0] = Bl[brb]; bl2[nt][1] = Bl[brb + 4];
            }
            #pragma unroll
            for (int mt = 0; mt < 4; mt++) {
                int arb = (wr * 64 + mt * 16 + grp) * AST + k16 * 8 + q;
                uint32_t ah[4], al[4];
                ah[0] = Ah[arb];     ah[1] = Ah[arb + 160];
                ah[2] = Ah[arb + 4]; ah[3] = Ah[arb + 164];
                al[0] = Al[arb];     al[1] = Al[arb + 160];
                al[2] = Al[arb + 4]; al[3] = Al[arb + 164];
                #pragma unroll
                for (int nt = 0; nt < 4; nt++) {
                    mma_bf16(c[mt][nt], ah, bh2[nt]);
                    mma_bf16(c[mt][nt], ah, bl2[nt]);
                    mma_bf16(c[mt][nt], al, bh2[nt]);
                }
            }
        }
    }

    float* S = S_out + (size_t)bh * Sn * Sn;
    float psum[4][2];
    #pragma unroll
    for (int mt = 0; mt < 4; mt++) { psum[mt][0] = 0.f; psum[mt][1] = 0.f; }

    #pragma unroll
    for (int mt = 0; mt < 4; mt++) {
        #pragma unroll
        for (int nt = 0; nt < 4; nt++) {
            int col = col0 + wc * 32 + nt * 8 + 2 * q;
            int r0  = row0 + wr * 64 + mt * 16 + grp;
            #pragma unroll
            for (int half = 0; half < 2; half++) {
                int r = r0 + half * 8;
                float2 v = make_float2(c[mt][nt][2*half], c[mt][nt][2*half + 1]);
                float rb = s_rb[r - row0];
                v.x = v.x * 0.125f + rb;
                v.y = v.y * 0.125f + rb;
                int2 m2 = *(const int2*)&mask[(size_t)r * Sn + col];
                if (m2.x == 0) v.x = -1e9f;
                if (m2.y == 0) v.y = -1e9f;
                psum[mt][half] += __expf(v.x) + __expf(v.y);
                *(float2*)&S[(size_t)r * Sn + col] = v;
            }
        }
    }
    // reduce expsum across q lanes, accumulate per-row into smem then gmem
    #pragma unroll
    for (int mt = 0; mt < 4; mt++) {
        #pragma unroll
        for (int half = 0; half < 2; half++) {
            float t = psum[mt][half];
            t += __shfl_xor_sync(0xffffffffu, t, 1);
            t += __shfl_xor_sync(0xffffffffu, t, 2);
            if (q == 0)
                atomicAdd(&s_sum[wr * 64 + mt * 16 + half * 8 + grp], t);
        }
    }
    __syncthreads();
    if (tid < 128)
        atomicAdd(&rowsum[(size_t)bh * Sn + row0 + tid], s_sum[tid]);
}

// ================= attention phase C: p=exp(S)/sum, write P, ctx = P @ V ===
constexpr int PV_APL   = 128 * AST;
constexpr int PV_BPL   = 64 * AST;
constexpr int PV_STAGE = 2 * PV_APL + 2 * PV_BPL;
constexpr int PV_SMEM  = 2 * PV_STAGE * 4;

__global__ __launch_bounds__(256)
void attn_pv(float* __restrict__ Pm, const float* __restrict__ rowsum,
             const __nv_bfloat16* __restrict__ vth, const __nv_bfloat16* __restrict__ vtl,
             __nv_bfloat16* __restrict__ ctxh, __nv_bfloat16* __restrict__ ctxl)
{
    extern __shared__ uint32_t smw[];
    __shared__ float s_inv[128];
    const int tid  = threadIdx.x;
    const int wid  = tid >> 5, lane = tid & 31;
    const int grp  = lane >> 2, q = lane & 3;
    const int bh = blockIdx.y, b = bh >> 3, h = bh & 7;
    const int m0 = blockIdx.x * 128;

    float* A = Pm + (size_t)bh * Sn * Sn;
    const __nv_bfloat16* Bh_ = vth + (size_t)bh * DKn * Sn;
    const __nv_bfloat16* Bl_ = vtl + (size_t)bh * DKn * Sn;

    if (tid < 128) s_inv[tid] = 1.f / rowsum[(size_t)bh * Sn + m0 + tid];
    __syncthreads();

    float c[8][4];
    #pragma unroll
    for (int nt = 0; nt < 8; nt++)
        #pragma unroll
        for (int e = 0; e < 4; e++) c[nt][e] = 0.f;

    const int T = Sn / KC;   // 64
    float4 ra[4]; uint4 rbh, rbl;

    auto stage_A = [&](uint32_t* stg, int k0) {
        #pragma unroll
        for (int it = 0; it < 4; it++) {
            int idx = tid + it * 256;
            int r = idx >> 3, f = idx & 7;
            float4 v = ra[it];
            float inv = s_inv[r];
            v.x = __expf(v.x) * inv; v.y = __expf(v.y) * inv;
            v.z = __expf(v.z) * inv; v.w = __expf(v.w) * inv;
            *(float4*)&A[(size_t)(m0 + r) * Sn + k0 + f * 4] = v;   // final attn
            int w = r * AST + f * 2;
            uint32_t h0, h1, l0, l1;
            split2(v.x, v.y, h0, l0);
            split2(v.z, v.w, h1, l1);
            stg[w] = h0; stg[w + 1] = h1;
            stg[PV_APL + w] = l0; stg[PV_APL + w + 1] = l1;
        }
        int r = tid >> 2, f = tid & 3;
        int w = r * AST + f * 4;
        *(uint4*)&stg[2 * PV_APL + w] = rbh;
        *(uint4*)&stg[2 * PV_APL + PV_BPL + w] = rbl;
    };
    auto ldg_AB = [&](int k0) {
        #pragma unroll
        for (int it = 0; it < 4; it++) {
            int idx = tid + it * 256;
            int r = idx >> 3, f = idx & 7;
            ra[it] = *(const float4*)&A[(size_t)(m0 + r) * Sn + k0 + f * 4];
        }
        int r = tid >> 2, f = tid & 3;
        rbh = *(const uint4*)&Bh_[(size_t)r * Sn + k0 + f * 8];
        rbl = *(const uint4*)&Bl_[(size_t)r * Sn + k0 + f * 8];
    };

    ldg_AB(0);
    stage_A(smw, 0);
    __syncthreads();

    for (int i = 0; i < T; i++) {
        const uint32_t* stg = smw + (i & 1) * PV_STAGE;
        const uint32_t* Ah = stg;
        const uint32_t* Al = stg + PV_APL;
        const uint32_t* Bhp = stg + 2 * PV_APL;
        const uint32_t* Blp = stg + 2 * PV_APL + PV_BPL;

        if (i + 1 < T) ldg_AB((i + 1) * KC);

        #pragma unroll
        for (int k16 = 0; k16 < 2; k16++) {
            int arb = (wid * 16 + grp) * AST + k16 * 8 + q;
            uint32_t ah[4], al[4];
            ah[0] = Ah[arb];     ah[1] = Ah[arb + 160];
            ah[2] = Ah[arb + 4]; ah[3] = Ah[arb + 164];
            al[0] = Al[arb];     al[1] = Al[arb + 160];
            al[2] = Al[arb + 4]; al[3] = Al[arb + 164];
            #pragma unroll
            for (int nt = 0; nt < 8; nt++) {
                int brb = (nt * 8 + grp) * AST + k16 * 8 + q;
                uint32_t bh2[2], bl2[2];
                bh2[0] = Bhp[brb]; bh2[1] = Bhp[brb + 4];
                bl2[0] = Blp[brb]; bl2[1] = Blp[brb + 4];
                mma_bf16(c[nt], ah, bh2);
                mma_bf16(c[nt], ah, bl2);
                mma_bf16(c[nt], al, bh2);
            }
        }
        __syncthreads();
        if (i + 1 < T) {
            stage_A(smw + ((i + 1) & 1) * PV_STAGE, (i + 1) * KC);
            __syncthreads();
        }
    }

    #pragma unroll
    for (int nt = 0; nt < 8; nt++) {
        int col = h * DKn + nt * 8 + 2 * q;
        int r0  = m0 + wid * 16 + grp;
        uint32_t hw, lw;
        split2(c[nt][0], c[nt][1], hw, lw);
        *(uint32_t*)&ctxh[(size_t)(b * Sn + r0) * Dn + col] = hw;
        *(uint32_t*)&ctxl[(size_t)(b * Sn + r0) * Dn + col] = lw;
        split2(c[nt][2], c[nt][3], hw, lw);
        *(uint32_t*)&ctxh[(size_t)(b * Sn + r0 + 8) * Dn + col] = hw;
        *(uint32_t*)&ctxl[(size_t)(b * Sn + r0 + 8) * Dn + col] = lw;
    }
}

// ============================ small utility kernels ========================
__global__ __launch_bounds__(256)
void zero_f32(float* __restrict__ p, int n)
{
    int i = blockIdx.x * 256 + threadIdx.x;
    if (i < n) p[i] = 0.f;
}

// fp32 -> bf16 hi/lo planes (contiguous)
__global__ __launch_bounds__(256)
void split_planes(const float* __restrict__ src, __nv_bfloat16* __restrict__ h,
                  __nv_bfloat16* __restrict__ l, int n4)
{
    int i = blockIdx.x * 256 + threadIdx.x;
    if (i >= n4) return;
    float4 v = ((const float4*)src)[i];
    uint32_t h0, l0, h1, l1;
    split2(v.x, v.y, h0, l0);
    split2(v.z, v.w, h1, l1);
    ((uint2*)h)[i] = make_uint2(h0, h1);
    ((uint2*)l)[i] = make_uint2(l0, l1);
}

// W[K,N] -> Wt[N,K] bf16 hi/lo planes
__global__ __launch_bounds__(256)
void transpose_w(const float* __restrict__ W, __nv_bfloat16* __restrict__ Wth,
                 __nv_bfloat16* __restrict__ Wtl, int K, int N)
{
    __shared__ float t[32][33];
    int x = blockIdx.x * 32 + threadIdx.x;
    #pragma unroll
    for (int j = 0; j < 4; j++)
        t[threadIdx.y + j * 8][threadIdx.x] =
            W[(size_t)(blockIdx.y * 32 + threadIdx.y + j * 8) * N + x];
    __syncthreads();
    int x2 = blockIdx.y * 32 + threadIdx.x;
    #pragma unroll
    for (int j = 0; j < 4; j++) {
        float v = t[threadIdx.x][threadIdx.y + j * 8];
        __nv_bfloat16 hi = __float2bfloat16_rn(v);
        size_t o = (size_t)(blockIdx.x * 32 + threadIdx.y + j * 8) * K + x2;
        Wth[o] = hi;
        Wtl[o] = __float2bfloat16_rn(v - __bfloat162float(hi));
    }
}

// V slice of qkv planes -> vt[bh][64][Sn] bf16 hi/lo
__global__ __launch_bounds__(256)
void transpose_v(const __nv_bfloat16* __restrict__ qh, const __nv_bfloat16* __restrict__ ql,
                 __nv_bfloat16* __restrict__ vth, __nv_bfloat16* __restrict__ vtl)
{
    __shared__ float t[32][33];
    const int bh = blockIdx.z, b = bh >> 3, h = bh & 7;
    const int s0 = blockIdx.x * 32;
    const int d0 = blockIdx.y * 32;
    const int vcol = 2 * Dn + h * DKn;
    #pragma unroll
    for (int j = 0; j < 4; j++) {
        size_t o = (size_t)(b * Sn + s0 + threadIdx.y + j * 8) * QKVN + vcol + d0 + threadIdx.x;
        t[threadIdx.y + j * 8][threadIdx.x] =
            __bfloat162float(qh[o]) + __bfloat162float(ql[o]);
    }
    __syncthreads();
    #pragma unroll
    for (int j = 0; j < 4; j++) {
        float v = t[threadIdx.x][threadIdx.y + j * 8];
        __nv_bfloat16 hi = __float2bfloat16_rn(v);
        size_t o = ((size_t)bh * DKn + d0 + threadIdx.y + j * 8) * Sn + s0 + threadIdx.x;
        vth[o] = hi;
        vtl[o] = __float2bfloat16_rn(v - __bfloat162float(hi));
    }
}

// ---------------------------------------------------------------------------
// out = LayerNorm(a + r) * g + b   (+ optional bf16 hi/lo planes of out)
// ---------------------------------------------------------------------------
__global__ __launch_bounds__(256)
void add_ln(const float* __restrict__ a, const float* __restrict__ r,
            const float* __restrict__ g, const float* __restrict__ be,
            float* __restrict__ out, __nv_bfloat16* __restrict__ oh,
            __nv_bfloat16* __restrict__ ol)
{
    const int row = blockIdx.x, tid = threadIdx.x;
    const float* ap = a + (size_t)row * Dn;
    const float* rp = r + (size_t)row * Dn;
    float v0 = ap[tid]       + rp[tid];
    float v1 = ap[tid + 256] + rp[tid + 256];

    __shared__ float red[8];
    __shared__ float s_mu, s_inv;
    const int w = tid >> 5, lane = tid & 31;

    float s = v0 + v1;
    #pragma unroll
    for (int o = 16; o > 0; o >>= 1) s += __shfl_xor_sync(0xffffffffu, s, o);
    if (lane == 0) red[w] = s;
    __syncthreads();
    if (tid < 32) {
        float t = (tid < 8) ? red[tid] : 0.f;
        #pragma unroll
        for (int o = 4; o > 0; o >>= 1) t += __shfl_xor_sync(0xffffffffu, t, o);
        if (tid == 0) s_mu = t * (1.f / Dn);
    }
    __syncthreads();
    float mu = s_mu;
    float d0 = v0 - mu, d1 = v1 - mu;

    float qv = d0*d0 + d1*d1;
    #pragma unroll
    for (int o = 16; o > 0; o >>= 1) qv += __shfl_xor_sync(0xffffffffu, qv, o);
    __syncthreads();
    if (lane == 0) red[w] = qv;
    __syncthreads();
    if (tid < 32) {
        float t = (tid < 8) ? red[tid] : 0.f;
        #pragma unroll
        for (int o = 4; o > 0; o >>= 1) t += __shfl_xor_sync(0xffffffffu, t, o);
        if (tid == 0) s_inv = rsqrtf(t * (1.f / Dn) + 1e-6f);
    }
    __syncthreads();
    float inv = s_inv;
    float o0 = d0 * inv * g[tid]       + be[tid];
    float o1 = d1 * inv * g[tid + 256] + be[tid + 256];
    float* op = out + (size_t)row * Dn;
    op[tid]       = o0;
    op[tid + 256] = o1;
    if (oh) {
        __nv_bfloat16 h0 = __float2bfloat16_rn(o0);
        __nv_bfloat16 h1 = __float2bfloat16_rn(o1);
        size_t base = (size_t)row * Dn;
        oh[base + tid]       = h0;
        oh[base + tid + 256] = h1;
        ol[base + tid]       = __float2bfloat16_rn(o0 - __bfloat162float(h0));
        ol[base + tid + 256] = __float2bfloat16_rn(o1 - __bfloat162float(h1));
    }
}

// ---------------------------------------------------------------------------
extern "C" void kernel_launch(void* const* d_in, const int* in_sizes, int n_in,
                              void* d_out, int out_size)
{
    const float* x    = (const float*)d_in[0];
    const float* sw   = (const float*)d_in[1];
    const int*   mask = (const int*)  d_in[2];
    const float* Wq   = (const float*)d_in[3];
    const float* Wk   = (const float*)d_in[4];
    const float* Wv   = (const float*)d_in[5];
    const float* Wo   = (const float*)d_in[6];
    const float* bo   = (const float*)d_in[7];
    const float* sa   = (const float*)d_in[8];
    const float* tb   = (const float*)d_in[9];
    const float* ln1g = (const float*)d_in[10];
    const float* ln1b = (const float*)d_in[11];
    const float* ln2g = (const float*)d_in[12];
    const float* ln2b = (const float*)d_in[13];
    const float* W1   = (const float*)d_in[14];
    const float* b1   = (const float*)d_in[15];
    const float* W2   = (const float*)d_in[16];
    const float* b2   = (const float*)d_in[17];

    float* out_x2   = (float*)d_out;
    float* out_attn = (float*)d_out + (size_t)BSn * Dn;

    float *x1, *t2, *rowsum;
    __nv_bfloat16 *xh, *xl, *qkvh, *qkvl, *ctxh, *ctxl, *x1h, *x1l, *ffh, *ffl;
    __nv_bfloat16 *wqkv_h, *wqkv_l, *wo_h, *wo_l, *w1_h, *w1_l, *w2_h, *w2_l, *vth, *vtl;
    cudaGetSymbolAddress((void**)&x1,     g_x1);
    cudaGetSymbolAddress((void**)&t2,     g_t2);
    cudaGetSymbolAddress((void**)&rowsum, g_rowsum);
    cudaGetSymbolAddress((void**)&xh,     g_x_h);
    cudaGetSymbolAddress((void**)&xl,     g_x_l);
    cudaGetSymbolAddress((void**)&qkvh,   g_qkv_h);
    cudaGetSymbolAddress((void**)&qkvl,   g_qkv_l);
    cudaGetSymbolAddress((void**)&ctxh,   g_ctx_h);
    cudaGetSymbolAddress((void**)&ctxl,   g_ctx_l);
    cudaGetSymbolAddress((void**)&x1h,    g_x1_h);
    cudaGetSymbolAddress((void**)&x1l,    g_x1_l);
    cudaGetSymbolAddress((void**)&ffh,    g_ff_h);
    cudaGetSymbolAddress((void**)&ffl,    g_ff_l);
    cudaGetSymbolAddress((void**)&wqkv_h, g_wqkv_h);
    cudaGetSymbolAddress((void**)&wqkv_l, g_wqkv_l);
    cudaGetSymbolAddress((void**)&wo_h,   g_wo_h);
    cudaGetSymbolAddress((void**)&wo_l,   g_wo_l);
    cudaGetSymbolAddress((void**)&w1_h,   g_w1_h);
    cudaGetSymbolAddress((void**)&w1_l,   g_w1_l);
    cudaGetSymbolAddress((void**)&w2_h,   g_w2_h);
    cudaGetSymbolAddress((void**)&w2_l,   g_w2_l);
    cudaGetSymbolAddress((void**)&vth,    g_vt_h);
    cudaGetSymbolAddress((void**)&vtl,    g_vt_l);

    cudaFuncSetAttribute(gemm_mma<0,false,true>, cudaFuncAttributeMaxDynamicSharedMemorySize, GEMM_SMEM);
    cudaFuncSetAttribute(gemm_mma<1,true,false>, cudaFuncAttributeMaxDynamicSharedMemorySize, GEMM_SMEM);
    cudaFuncSetAttribute(gemm_mma<2,false,true>, cudaFuncAttributeMaxDynamicSharedMemorySize, GEMM_SMEM);
    cudaFuncSetAttribute(attn_score, cudaFuncAttributeMaxDynamicSharedMemorySize, GEMM_SMEM);
    cudaFuncSetAttribute(attn_pv,    cudaFuncAttributeMaxDynamicSharedMemorySize, PV_SMEM);

    dim3 tb8(32, 8);
    dim3 blk(256);

    // weight transposes + input split
    transpose_w<<<dim3(Dn/32,  Dn/32),  tb8>>>(Wq, wqkv_h,            wqkv_l,            Dn, Dn);
    transpose_w<<<dim3(Dn/32,  Dn/32),  tb8>>>(Wk, wqkv_h + Dn*Dn,    wqkv_l + Dn*Dn,    Dn, Dn);
    transpose_w<<<dim3(Dn/32,  Dn/32),  tb8>>>(Wv, wqkv_h + 2*Dn*Dn,  wqkv_l + 2*Dn*Dn,  Dn, Dn);
    transpose_w<<<dim3(Dn/32,  Dn/32),  tb8>>>(Wo, wo_h, wo_l, Dn, Dn);
    transpose_w<<<dim3(DFFn/32, Dn/32), tb8>>>(W1, w1_h, w1_l, Dn, DFFn);
    transpose_w<<<dim3(Dn/32, DFFn/32), tb8>>>(W2, w2_h, w2_l, DFFn, Dn);
    split_planes<<<(BSn*Dn/4 + 255)/256, blk>>>(x, xh, xl, BSn*Dn/4);
    zero_f32<<<(BHn*Sn + 255)/256, blk>>>(rowsum, BHn*Sn);

    // fused QKV projection -> planes
    gemm_mma<0,false,true><<<dim3(QKVN/128, BSn/128), blk, GEMM_SMEM>>>(
        xh, xl, wqkv_h, wqkv_l, nullptr, nullptr, qkvh, qkvl, BSn, QKVN, Dn);

    // V transpose for PV phase
    transpose_v<<<dim3(Sn/32, DKn/32, BHn), tb8>>>(qkvh, qkvl, vth, vtl);

    // attention: raw scores + expsums -> normalize-in-pv (writes final attn)
    attn_score<<<dim3(Sn/128, Sn/128, BHn), blk, GEMM_SMEM>>>(
        qkvh, qkvl, sw, mask, sa, tb, out_attn, rowsum);
    attn_pv<<<dim3(Sn/128, BHn), blk, PV_SMEM>>>(
        out_attn, rowsum, vth, vtl, ctxh, ctxl);

    // output projection + bias
    gemm_mma<1,true,false><<<dim3(Dn/128, BSn/128), blk, GEMM_SMEM>>>(
        ctxh, ctxl, wo_h, wo_l, bo, t2, nullptr, nullptr, BSn, Dn, Dn);
    add_ln<<<BSn, blk>>>(x, t2, ln1g, ln1b, x1, x1h, x1l);

    // FFN
    gemm_mma<2,false,true><<<dim3(DFFn/128, BSn/128), blk, GEMM_SMEM>>>(
        x1h, x1l, w1_h, w1_l, b1, nullptr, ffh, ffl, BSn, DFFn, Dn);
    gemm_mma<1,true,false><<<dim3(Dn/128, BSn/128), blk, GEMM_SMEM>>>(
        ffh, ffl, w2_h, w2_l, b2, t2, nullptr, nullptr, BSn, Dn, DFFn);

    add_ln<<<BSn, blk>>>(x1, t2, ln2g, ln2b, out_x2, nullptr, nullptr);
}